// round 11
// baseline (speedup 1.0000x reference)
#include <cuda_runtime.h>
#include <cuda_bf16.h>
#include <math.h>
#include <stdint.h>

#define BB  4
#define SS  1024
#define DD  1024
#define HH  16
#define DHH 64
#define NFLAT 3072   // q:0-1023, k:1024-2047, v:2048-3071

// ---- persistent scratch (no allocations allowed) ----
__device__ float g_z[BB*HH*SS*DHH];     // per-head attention output

__device__ __nv_bfloat16 g_xhi[BB*SS*DD];
__device__ __nv_bfloat16 g_xlo[BB*SS*DD];
__device__ __nv_bfloat16 g_whi[NFLAT*DD];   // transposed: [n][k]
__device__ __nv_bfloat16 g_wlo[NFLAT*DD];

// attention operands, hi/lo split bf16, all [bh][s][e]
__device__ __nv_bfloat16 g_qhi[64*SS*DHH];
__device__ __nv_bfloat16 g_qlo[64*SS*DHH];
__device__ __nv_bfloat16 g_khi[64*SS*DHH];
__device__ __nv_bfloat16 g_klo[64*SS*DHH];
__device__ __nv_bfloat16 g_vhi[64*SS*DHH];
__device__ __nv_bfloat16 g_vlo[64*SS*DHH];

// ============================================================
// helpers
// ============================================================
__device__ __forceinline__ uint32_t smem_u32(const void* p) {
    uint32_t a;
    asm("{ .reg .u64 t; cvta.to.shared.u64 t, %1; cvt.u32.u64 %0, t; }"
        : "=r"(a) : "l"(p));
    return a;
}

#define CP16(dst, src) \
    asm volatile("cp.async.cg.shared.global [%0], [%1], 16;" \
                 :: "r"(dst), "l"(src) : "memory")
#define CP_COMMIT() asm volatile("cp.async.commit_group;" ::: "memory")
#define CP_WAIT1()  asm volatile("cp.async.wait_group 1;" ::: "memory")
#define CP_WAIT0()  asm volatile("cp.async.wait_group 0;" ::: "memory")

#define LDSM_X4(R, addr) \
    asm volatile("ldmatrix.sync.aligned.m8n8.x4.shared.b16 {%0,%1,%2,%3}, [%4];" \
                 : "=r"((R)[0]), "=r"((R)[1]), "=r"((R)[2]), "=r"((R)[3]) \
                 : "r"(addr))

#define LDSM_X4_T(R, addr) \
    asm volatile("ldmatrix.sync.aligned.m8n8.x4.trans.shared.b16 {%0,%1,%2,%3}, [%4];" \
                 : "=r"((R)[0]), "=r"((R)[1]), "=r"((R)[2]), "=r"((R)[3]) \
                 : "r"(addr))

#define MMA16816(D, A, B) \
    asm volatile("mma.sync.aligned.m16n8k16.row.col.f32.bf16.bf16.f32 " \
                 "{%0,%1,%2,%3}, {%4,%5,%6,%7}, {%8,%9}, {%0,%1,%2,%3};" \
                 : "+f"((D)[0]), "+f"((D)[1]), "+f"((D)[2]), "+f"((D)[3]) \
                 : "r"((A)[0]), "r"((A)[1]), "r"((A)[2]), "r"((A)[3]), \
                   "r"((B)[0]), "r"((B)[1]))

__device__ __forceinline__ uint32_t pack_bf16x2(float a, float b) {
    uint32_t r;
    asm("cvt.rn.bf16x2.f32 %0, %1, %2;" : "=r"(r) : "f"(b), "f"(a));
    return r;
}

// ============================================================
// Fused split kernel
// ============================================================
__global__ __launch_bounds__(256) void split_all_kernel(
    const float* __restrict__ x,
    const float* __restrict__ Wq, const float* __restrict__ Wk,
    const float* __restrict__ Wv)
{
    const int tid = threadIdx.x;
    if (blockIdx.x < 4096) {
        int i4 = blockIdx.x * 256 + tid;
        float4 v = ((const float4*)x)[i4];
        __nv_bfloat16 h0 = __float2bfloat16(v.x);
        __nv_bfloat16 h1 = __float2bfloat16(v.y);
        __nv_bfloat16 h2 = __float2bfloat16(v.z);
        __nv_bfloat16 h3 = __float2bfloat16(v.w);
        __nv_bfloat16 l0 = __float2bfloat16(v.x - __bfloat162float(h0));
        __nv_bfloat16 l1 = __float2bfloat16(v.y - __bfloat162float(h1));
        __nv_bfloat16 l2 = __float2bfloat16(v.z - __bfloat162float(h2));
        __nv_bfloat16 l3 = __float2bfloat16(v.w - __bfloat162float(h3));
        __nv_bfloat162* ph = (__nv_bfloat162*)g_xhi;
        __nv_bfloat162* pl = (__nv_bfloat162*)g_xlo;
        ph[i4 * 2]     = __nv_bfloat162(h0, h1);
        ph[i4 * 2 + 1] = __nv_bfloat162(h2, h3);
        pl[i4 * 2]     = __nv_bfloat162(l0, l1);
        pl[i4 * 2 + 1] = __nv_bfloat162(l2, l3);
        return;
    }
    __shared__ float ts[64][65];
    const int bid = blockIdx.x - 4096;
    const int hf = bid >> 4;
    const int kc = bid & 15;
    const int t = hf >> 4;
    const int h = hf & 15;
    const int k0 = kc * 64;
    const float* W = (t == 0 ? Wq : (t == 1 ? Wk : Wv)) + (size_t)h * DD * DHH;

    #pragma unroll
    for (int j = 0; j < 16; j++) {
        int lin = j * 256 + tid;
        int kk = lin >> 6, e = lin & 63;
        ts[kk][e] = W[(size_t)(k0 + kk) * DHH + e];
    }
    __syncthreads();
    #pragma unroll
    for (int j = 0; j < 16; j++) {
        int lin = j * 256 + tid;
        int e = lin >> 6, kk = lin & 63;
        float v = ts[kk][e];
        __nv_bfloat16 hi = __float2bfloat16(v);
        __nv_bfloat16 lo = __float2bfloat16(v - __bfloat162float(hi));
        size_t o = ((size_t)(t * 1024 + h * 64 + e)) * DD + k0 + kk;
        g_whi[o] = hi;
        g_wlo[o] = lo;
    }
}

// ============================================================
// QKV projection (unchanged from R10 — 71% of HMMA peak)
// ============================================================
#define T_AH 0u
#define T_AL 16384u
#define T_BH 32768u
#define T_BL 49152u
#define STAGE_BYTES 65536u

__device__ __forceinline__ void qkv_load_stage(uint32_t sb, int stage,
                                               int m0, int n0, int k0)
{
    const int tid = threadIdx.x;
    const char* pAh = (const char*)g_xhi;
    const char* pAl = (const char*)g_xlo;
    const char* pBh = (const char*)g_whi;
    const char* pBl = (const char*)g_wlo;
    uint32_t base = sb + stage * STAGE_BYTES;
    #pragma unroll
    for (int i = 0; i < 4; i++) {
        int chunk = tid + i * 256;
        int r = chunk >> 3;
        int c = chunk & 7;
        uint32_t off = r * 128 + (((uint32_t)(c ^ (r & 7))) << 4);
        size_t ga = ((size_t)(m0 + r) * DD + k0) * 2 + c * 16;
        size_t gb = ((size_t)(n0 + r) * DD + k0) * 2 + c * 16;
        CP16(base + T_AH + off, pAh + ga);
        CP16(base + T_AL + off, pAl + ga);
        CP16(base + T_BH + off, pBh + gb);
        CP16(base + T_BL + off, pBl + gb);
    }
}

__global__ __launch_bounds__(256) void qkv_mma_kernel(
    const float* __restrict__ bq, const float* __restrict__ bk,
    const float* __restrict__ bv)
{
    extern __shared__ char dsm[];
    const uint32_t sb = smem_u32(dsm);

    const int tid = threadIdx.x;
    const int wid = tid >> 5;
    const int lane = tid & 31;
    const int warp_m = wid >> 2;
    const int warp_n = wid & 3;
    const int n0 = blockIdx.x * 128;
    const int m0 = blockIdx.y * 128;

    float acc[4][4][4];
    #pragma unroll
    for (int i = 0; i < 4; i++)
        #pragma unroll
        for (int j = 0; j < 4; j++)
            #pragma unroll
            for (int v = 0; v < 4; v++) acc[i][j][v] = 0.f;

    qkv_load_stage(sb, 0, m0, n0, 0);
    CP_COMMIT();

    for (int kb = 0; kb < 16; kb++) {
        if (kb < 15) {
            qkv_load_stage(sb, (kb + 1) & 1, m0, n0, (kb + 1) * 64);
            CP_COMMIT();
            CP_WAIT1();
        } else {
            CP_WAIT0();
        }
        __syncthreads();

        const uint32_t stg = sb + (kb & 1) * STAGE_BYTES;
        #pragma unroll
        for (int s = 0; s < 4; s++) {
            uint32_t ah[16], al[16];
            #pragma unroll
            for (int mt = 0; mt < 4; mt++) {
                int r = warp_m * 64 + mt * 16 + (lane & 15);
                int c = 2 * s + (lane >> 4);
                uint32_t off = r * 128 + (((uint32_t)(c ^ (r & 7))) << 4);
                LDSM_X4(&ah[mt * 4], stg + T_AH + off);
                LDSM_X4(&al[mt * 4], stg + T_AL + off);
            }
            uint32_t bh[8], bl[8];
            #pragma unroll
            for (int bt = 0; bt < 2; bt++) {
                int nr = warp_n * 32 + bt * 16 + ((lane >> 4) << 3) + (lane & 7);
                int c = 2 * s + ((lane >> 3) & 1);
                uint32_t off = nr * 128 + (((uint32_t)(c ^ (nr & 7))) << 4);
                LDSM_X4(&bh[bt * 4], stg + T_BH + off);
                LDSM_X4(&bl[bt * 4], stg + T_BL + off);
            }
            #pragma unroll
            for (int mt = 0; mt < 4; mt++)
                #pragma unroll
                for (int nt = 0; nt < 4; nt++) {
                    int bi = (nt >> 1) * 4 + (nt & 1) * 2;
                    MMA16816(acc[mt][nt], &ah[mt * 4], &bh[bi]);
                }
            #pragma unroll
            for (int mt = 0; mt < 4; mt++)
                #pragma unroll
                for (int nt = 0; nt < 4; nt++) {
                    int bi = (nt >> 1) * 4 + (nt & 1) * 2;
                    MMA16816(acc[mt][nt], &ah[mt * 4], &bl[bi]);
                }
            #pragma unroll
            for (int mt = 0; mt < 4; mt++)
                #pragma unroll
                for (int nt = 0; nt < 4; nt++) {
                    int bi = (nt >> 1) * 4 + (nt & 1) * 2;
                    MMA16816(acc[mt][nt], &al[mt * 4], &bh[bi]);
                }
        }
        __syncthreads();
    }

    #pragma unroll
    for (int nt = 0; nt < 4; nt++) {
        int n = n0 + warp_n * 32 + nt * 8 + (lane & 3) * 2;
        int t = n >> 10;
        int h = (n >> 6) & 15;
        int e = n & 63;
        const float* bias = (t == 0 ? bq : (t == 1 ? bk : bv));
        __nv_bfloat16* dhi = (t == 0 ? g_qhi : (t == 1 ? g_khi : g_vhi));
        __nv_bfloat16* dlo = (t == 0 ? g_qlo : (t == 1 ? g_klo : g_vlo));
        float b0v = bias[h * 64 + e];
        float b1v = bias[h * 64 + e + 1];
        #pragma unroll
        for (int mt = 0; mt < 4; mt++) {
            #pragma unroll
            for (int half = 0; half < 2; half++) {
                int row = m0 + warp_m * 64 + mt * 16 + (lane >> 2) + half * 8;
                int b = row >> 10;
                int s = row & 1023;
                int bh = b * HH + h;
                float v0 = acc[mt][nt][half * 2]     + b0v;
                float v1 = acc[mt][nt][half * 2 + 1] + b1v;
                __nv_bfloat16 h0 = __float2bfloat16(v0);
                __nv_bfloat16 h1 = __float2bfloat16(v1);
                __nv_bfloat16 l0 = __float2bfloat16(v0 - __bfloat162float(h0));
                __nv_bfloat16 l1 = __float2bfloat16(v1 - __bfloat162float(h1));
                size_t o = ((size_t)(bh << 10) + s) * 64 + e;
                *(__nv_bfloat162*)&dhi[o] = __nv_bfloat162(h0, h1);
                *(__nv_bfloat162*)&dlo[o] = __nv_bfloat162(l0, l1);
            }
        }
    }
}

// ============================================================
// Flash attention: 128-thread CTAs (4 warps, 64 q-rows), KT=64,
// 2 stages. smem 80KB -> 2 CTAs/SM so softmax bubbles overlap
// with the co-resident CTA's MMAs.
// stage: KH 0, KL 8K, VH 16K, VL 24K (32KB); stages at 0; Q at 64K.
// ============================================================
#define AST    0u
#define AST_SZ 32768u
#define AQ_H   65536u
#define AQ_L   73728u

__device__ __forceinline__ void attn_load_kv(uint32_t stg, int bh, int k0)
{
    const int tid = threadIdx.x;
    const char* kh = (const char*)g_khi;
    const char* kl = (const char*)g_klo;
    const char* vh = (const char*)g_vhi;
    const char* vl = (const char*)g_vlo;
    #pragma unroll
    for (int i = 0; i < 4; i++) {
        int ch = i * 128 + tid;        // 0..511
        int r = ch >> 3;               // 0..63
        int c = ch & 7;
        uint32_t off = r * 128 + (((uint32_t)(c ^ (r & 7))) << 4);
        size_t src = ((size_t)((bh << 10) + k0 + r)) * 128 + c * 16;
        CP16(stg + 0 + off, kh + src);
        CP16(stg + 8192 + off, kl + src);
        CP16(stg + 16384 + off, vh + src);
        CP16(stg + 24576 + off, vl + src);
    }
}

__global__ __launch_bounds__(128) void attn_mma_kernel()
{
    extern __shared__ char dsm[];
    const uint32_t sb = smem_u32(dsm);

    const int tid = threadIdx.x;
    const int wid = tid >> 5;          // 0..3
    const int lane = tid & 31;
    const int qt = 15 - blockIdx.x;    // heavy tiles first
    const int bh = blockIdx.y;
    const int q0 = qt * 64;
    const int n_kt = qt + 1;           // KT = 64

    {
        const char* qh = (const char*)g_qhi;
        const char* ql = (const char*)g_qlo;
        #pragma unroll
        for (int i = 0; i < 4; i++) {
            int ch = i * 128 + tid;    // 0..511
            int r = ch >> 3;           // 0..63
            int c = ch & 7;
            uint32_t off = r * 128 + (((uint32_t)(c ^ (r & 7))) << 4);
            size_t src = ((size_t)((bh << 10) + q0 + r)) * 128 + c * 16;
            CP16(sb + AQ_H + off, qh + src);
            CP16(sb + AQ_L + off, ql + src);
        }
        attn_load_kv(sb + AST, bh, 0);
        CP_COMMIT();
    }

    float o[8][4];
    #pragma unroll
    for (int i = 0; i < 8; i++)
        #pragma unroll
        for (int j = 0; j < 4; j++) o[i][j] = 0.f;
    float m[2] = {-1e30f, -1e30f};
    float l[2] = {0.f, 0.f};
    uint32_t qfh[16], qfl[16];
    const int wr0 = q0 + wid * 16;

    for (int kt = 0; kt < n_kt; kt++) {
        if (kt + 1 < n_kt) {
            attn_load_kv(sb + AST + ((kt + 1) & 1) * AST_SZ, bh, (kt + 1) * 64);
            CP_COMMIT();
            CP_WAIT1();
        } else {
            CP_WAIT0();
        }
        __syncthreads();

        if (kt == 0) {
            #pragma unroll
            for (int ks = 0; ks < 4; ks++) {
                int r = wid * 16 + (lane & 15);
                int c = 2 * ks + (lane >> 4);
                uint32_t off = r * 128 + (((uint32_t)(c ^ (r & 7))) << 4);
                LDSM_X4(&qfh[ks * 4], sb + AQ_H + off);
                LDSM_X4(&qfl[ks * 4], sb + AQ_L + off);
            }
        }

        const int k0 = kt * 64;
        const uint32_t stg = sb + AST + (kt & 1) * AST_SZ;

        // ---- S = Q K^T (product-major) ----
        float sc[8][4];
        #pragma unroll
        for (int i = 0; i < 8; i++)
            #pragma unroll
            for (int j = 0; j < 4; j++) sc[i][j] = 0.f;
        #pragma unroll
        for (int ks = 0; ks < 4; ks++) {
            uint32_t kfh[16], kfl[16];
            #pragma unroll
            for (int nt2 = 0; nt2 < 4; nt2++) {
                int nr = nt2 * 16 + ((lane >> 4) << 3) + (lane & 7);
                int c = 2 * ks + ((lane >> 3) & 1);
                uint32_t off = nr * 128 + (((uint32_t)(c ^ (nr & 7))) << 4);
                LDSM_X4(&kfh[nt2 * 4], stg + 0 + off);
                LDSM_X4(&kfl[nt2 * 4], stg + 8192 + off);
            }
            #pragma unroll
            for (int nt = 0; nt < 8; nt++) {
                int bi = (nt >> 1) * 4 + (nt & 1) * 2;
                MMA16816(sc[nt], &qfh[ks * 4], &kfh[bi]);
            }
            #pragma unroll
            for (int nt = 0; nt < 8; nt++) {
                int bi = (nt >> 1) * 4 + (nt & 1) * 2;
                MMA16816(sc[nt], &qfh[ks * 4], &kfl[bi]);
            }
            #pragma unroll
            for (int nt = 0; nt < 8; nt++) {
                int bi = (nt >> 1) * 4 + (nt & 1) * 2;
                MMA16816(sc[nt], &qfl[ks * 4], &kfh[bi]);
            }
        }
        // ---- online softmax over 64 cols ----
        const bool need_mask = (k0 + 63 > wr0);
        uint32_t ph[16], pl[16];
        float alpha[2];
        #pragma unroll
        for (int rs = 0; rs < 2; rs++) {
            int grow = wr0 + (lane >> 2) + rs * 8;
            float mx = -1e30f;
            #pragma unroll
            for (int nt = 0; nt < 8; nt++) {
                float v0 = sc[nt][rs * 2] * 0.125f;
                float v1 = sc[nt][rs * 2 + 1] * 0.125f;
                if (need_mask) {
                    int gc = k0 + nt * 8 + 2 * (lane & 3);
                    if (gc > grow) v0 = -1e30f;
                    if (gc + 1 > grow) v1 = -1e30f;
                }
                sc[nt][rs * 2] = v0;
                sc[nt][rs * 2 + 1] = v1;
                mx = fmaxf(mx, fmaxf(v0, v1));
            }
            mx = fmaxf(mx, __shfl_xor_sync(0xffffffffu, mx, 1));
            mx = fmaxf(mx, __shfl_xor_sync(0xffffffffu, mx, 2));
            float mn = fmaxf(m[rs], mx);
            alpha[rs] = __expf(m[rs] - mn);
            m[rs] = mn;
            float rsum = 0.f;
            #pragma unroll
            for (int nt = 0; nt < 8; nt++) {
                float p0 = __expf(sc[nt][rs * 2] - mn);
                float p1 = __expf(sc[nt][rs * 2 + 1] - mn);
                rsum += p0 + p1;
                uint32_t hp = pack_bf16x2(p0, p1);
                float r0 = p0 - __uint_as_float(hp << 16);
                float r1 = p1 - __uint_as_float(hp & 0xFFFF0000u);
                uint32_t lp = pack_bf16x2(r0, r1);
                int idx = (nt >> 1) * 4 + (nt & 1) * 2 + rs;
                ph[idx] = hp;
                pl[idx] = lp;
            }
            rsum += __shfl_xor_sync(0xffffffffu, rsum, 1);
            rsum += __shfl_xor_sync(0xffffffffu, rsum, 2);
            l[rs] = l[rs] * alpha[rs] + rsum;
            #pragma unroll
            for (int ne = 0; ne < 8; ne++) {
                o[ne][rs * 2] *= alpha[rs];
                o[ne][rs * 2 + 1] *= alpha[rs];
            }
        }
        // ---- O += P V (V via trans-ldmatrix, product-major) ----
        #pragma unroll
        for (int kp = 0; kp < 4; kp++) {
            uint32_t vfh[16], vfl[16];
            #pragma unroll
            for (int ne2 = 0; ne2 < 4; ne2++) {
                int r = kp * 16 + (lane & 15);
                int c = ne2 * 2 + (lane >> 4);
                uint32_t off = r * 128 + (((uint32_t)(c ^ (r & 7))) << 4);
                LDSM_X4_T(&vfh[ne2 * 4], stg + 16384 + off);
                LDSM_X4_T(&vfl[ne2 * 4], stg + 24576 + off);
            }
            #pragma unroll
            for (int ne = 0; ne < 8; ne++) {
                int bi = (ne >> 1) * 4 + (ne & 1) * 2;
                MMA16816(o[ne], &ph[kp * 4], &vfh[bi]);
            }
            #pragma unroll
            for (int ne = 0; ne < 8; ne++) {
                int bi = (ne >> 1) * 4 + (ne & 1) * 2;
                MMA16816(o[ne], &ph[kp * 4], &vfl[bi]);
            }
            #pragma unroll
            for (int ne = 0; ne < 8; ne++) {
                int bi = (ne >> 1) * 4 + (ne & 1) * 2;
                MMA16816(o[ne], &pl[kp * 4], &vfh[bi]);
            }
        }
        __syncthreads();
    }

    // ---- normalize + write ----
    #pragma unroll
    for (int rs = 0; rs < 2; rs++) {
        float inv = 1.f / l[rs];
        int row = wr0 + (lane >> 2) + rs * 8;
        #pragma unroll
        for (int ne = 0; ne < 8; ne++) {
            int e = ne * 8 + 2 * (lane & 3);
            float2 r2;
            r2.x = o[ne][rs * 2] * inv;
            r2.y = o[ne][rs * 2 + 1] * inv;
            *(float2*)&g_z[((size_t)(bh << 10) + row) * 64 + e] = r2;
        }
    }
}

// ============================================================
// FF with fused head-sum, 16 tokens/CTA (cuts Wf L2 traffic 4x)
// ============================================================
__device__ __forceinline__ float gelu_exact(float v)
{
    return 0.5f * v * (1.0f + erff(v * 0.70710678118654752f));
}

__global__ __launch_bounds__(256) void ff_kernel(const float* __restrict__ Wf,
                                                 const float* __restrict__ bf,
                                                 float* __restrict__ out)
{
    __shared__ float ssum[16][64];
    const int t0 = blockIdx.x * 16;
    const int tid = threadIdx.x;

    #pragma unroll
    for (int j = 0; j < 4; j++) {
        int idx = j * 256 + tid;       // 0..1023
        int t = idx >> 6;
        int e = idx & 63;
        int tok = t0 + t;
        int b = tok >> 10;
        int s = tok & 1023;
        const float* zp = g_z + ((size_t)(b * HH) * SS + s) * DHH + e;
        float acc = 0.f;
        #pragma unroll
        for (int h = 0; h < HH; h++) acc += zp[(size_t)h * SS * DHH];
        ssum[t][e] = acc;
    }
    __syncthreads();

    const int col = tid * 4;
    float acc[16][4];
    #pragma unroll
    for (int t = 0; t < 16; t++)
        #pragma unroll
        for (int j = 0; j < 4; j++) acc[t][j] = 0.f;

    #pragma unroll 4
    for (int e = 0; e < 64; e++) {
        float4 w = *(const float4*)&Wf[(size_t)e * DD + col];
        #pragma unroll
        for (int t = 0; t < 16; t++) {
            float sv = ssum[t][e];
            acc[t][0] += sv * w.x;
            acc[t][1] += sv * w.y;
            acc[t][2] += sv * w.z;
            acc[t][3] += sv * w.w;
        }
    }

    float4 b4 = *(const float4*)&bf[col];
    #pragma unroll
    for (int t = 0; t < 16; t++) {
        float4 r;
        r.x = gelu_exact(acc[t][0] + b4.x);
        r.y = gelu_exact(acc[t][1] + b4.y);
        r.z = gelu_exact(acc[t][2] + b4.z);
        r.w = gelu_exact(acc[t][3] + b4.w);
        *(float4*)&out[(size_t)(t0 + t) * DD + col] = r;
    }
}

// ============================================================
extern "C" void kernel_launch(void* const* d_in, const int* in_sizes, int n_in,
                              void* d_out, int out_size)
{
    const float* x  = (const float*)d_in[0];
    const float* Wq = (const float*)d_in[1];
    const float* bq = (const float*)d_in[2];
    const float* Wk = (const float*)d_in[3];
    const float* bk = (const float*)d_in[4];
    const float* Wv = (const float*)d_in[5];
    const float* bv = (const float*)d_in[6];
    const float* Wf = (const float*)d_in[7];
    const float* bf = (const float*)d_in[8];
    float* out = (float*)d_out;

    static const int QKV_SMEM = 131072;   // 2 stages x 64KB
    static const int ATT_SMEM = 81920;    // 2 stages x 32KB + Q 16KB
    cudaFuncSetAttribute(qkv_mma_kernel,
                         cudaFuncAttributeMaxDynamicSharedMemorySize, QKV_SMEM);
    cudaFuncSetAttribute(attn_mma_kernel,
                         cudaFuncAttributeMaxDynamicSharedMemorySize, ATT_SMEM);

    split_all_kernel<<<4096 + 768, 256>>>(x, Wq, Wk, Wv);

    dim3 gMMA(NFLAT / 128, (BB * SS) / 128);
    qkv_mma_kernel<<<gMMA, 256, QKV_SMEM>>>(bq, bk, bv);

    dim3 gAtt(16, 64);
    attn_mma_kernel<<<gAtt, 128, ATT_SMEM>>>();

    ff_kernel<<<(BB * SS) / 16, 256>>>(Wf, bf, out);
}

// round 12
// speedup vs baseline: 1.0618x; 1.0618x over previous
#include <cuda_runtime.h>
#include <cuda_bf16.h>
#include <math.h>
#include <stdint.h>

#define BB  4
#define SS  1024
#define DD  1024
#define HH  16
#define DHH 64
#define NFLAT 3072   // q:0-1023, k:1024-2047, v:2048-3071

// ---- persistent scratch (no allocations allowed) ----
__device__ float g_z[BB*HH*SS*DHH];     // per-head attention output

__device__ __nv_bfloat16 g_xhi[BB*SS*DD];
__device__ __nv_bfloat16 g_xlo[BB*SS*DD];
__device__ __nv_bfloat16 g_whi[NFLAT*DD];   // transposed: [n][k]
__device__ __nv_bfloat16 g_wlo[NFLAT*DD];

// attention operands, hi/lo split bf16, all [bh][s][e]
__device__ __nv_bfloat16 g_qhi[64*SS*DHH];
__device__ __nv_bfloat16 g_qlo[64*SS*DHH];
__device__ __nv_bfloat16 g_khi[64*SS*DHH];
__device__ __nv_bfloat16 g_klo[64*SS*DHH];
__device__ __nv_bfloat16 g_vhi[64*SS*DHH];
__device__ __nv_bfloat16 g_vlo[64*SS*DHH];

// ============================================================
// helpers
// ============================================================
__device__ __forceinline__ uint32_t smem_u32(const void* p) {
    uint32_t a;
    asm("{ .reg .u64 t; cvta.to.shared.u64 t, %1; cvt.u32.u64 %0, t; }"
        : "=r"(a) : "l"(p));
    return a;
}

#define CP16(dst, src) \
    asm volatile("cp.async.cg.shared.global [%0], [%1], 16;" \
                 :: "r"(dst), "l"(src) : "memory")
#define CP_COMMIT() asm volatile("cp.async.commit_group;" ::: "memory")
#define CP_WAIT1()  asm volatile("cp.async.wait_group 1;" ::: "memory")
#define CP_WAIT0()  asm volatile("cp.async.wait_group 0;" ::: "memory")

#define LDSM_X4(R, addr) \
    asm volatile("ldmatrix.sync.aligned.m8n8.x4.shared.b16 {%0,%1,%2,%3}, [%4];" \
                 : "=r"((R)[0]), "=r"((R)[1]), "=r"((R)[2]), "=r"((R)[3]) \
                 : "r"(addr))

#define LDSM_X4_T(R, addr) \
    asm volatile("ldmatrix.sync.aligned.m8n8.x4.trans.shared.b16 {%0,%1,%2,%3}, [%4];" \
                 : "=r"((R)[0]), "=r"((R)[1]), "=r"((R)[2]), "=r"((R)[3]) \
                 : "r"(addr))

#define MMA16816(D, A, B) \
    asm volatile("mma.sync.aligned.m16n8k16.row.col.f32.bf16.bf16.f32 " \
                 "{%0,%1,%2,%3}, {%4,%5,%6,%7}, {%8,%9}, {%0,%1,%2,%3};" \
                 : "+f"((D)[0]), "+f"((D)[1]), "+f"((D)[2]), "+f"((D)[3]) \
                 : "r"((A)[0]), "r"((A)[1]), "r"((A)[2]), "r"((A)[3]), \
                   "r"((B)[0]), "r"((B)[1]))

__device__ __forceinline__ uint32_t pack_bf16x2(float a, float b) {
    uint32_t r;
    asm("cvt.rn.bf16x2.f32 %0, %1, %2;" : "=r"(r) : "f"(b), "f"(a));
    return r;
}

// ============================================================
// Fused split kernel
// ============================================================
__global__ __launch_bounds__(256) void split_all_kernel(
    const float* __restrict__ x,
    const float* __restrict__ Wq, const float* __restrict__ Wk,
    const float* __restrict__ Wv)
{
    const int tid = threadIdx.x;
    if (blockIdx.x < 4096) {
        int i4 = blockIdx.x * 256 + tid;
        float4 v = ((const float4*)x)[i4];
        __nv_bfloat16 h0 = __float2bfloat16(v.x);
        __nv_bfloat16 h1 = __float2bfloat16(v.y);
        __nv_bfloat16 h2 = __float2bfloat16(v.z);
        __nv_bfloat16 h3 = __float2bfloat16(v.w);
        __nv_bfloat16 l0 = __float2bfloat16(v.x - __bfloat162float(h0));
        __nv_bfloat16 l1 = __float2bfloat16(v.y - __bfloat162float(h1));
        __nv_bfloat16 l2 = __float2bfloat16(v.z - __bfloat162float(h2));
        __nv_bfloat16 l3 = __float2bfloat16(v.w - __bfloat162float(h3));
        __nv_bfloat162* ph = (__nv_bfloat162*)g_xhi;
        __nv_bfloat162* pl = (__nv_bfloat162*)g_xlo;
        ph[i4 * 2]     = __nv_bfloat162(h0, h1);
        ph[i4 * 2 + 1] = __nv_bfloat162(h2, h3);
        pl[i4 * 2]     = __nv_bfloat162(l0, l1);
        pl[i4 * 2 + 1] = __nv_bfloat162(l2, l3);
        return;
    }
    __shared__ float ts[64][65];
    const int bid = blockIdx.x - 4096;
    const int hf = bid >> 4;
    const int kc = bid & 15;
    const int t = hf >> 4;
    const int h = hf & 15;
    const int k0 = kc * 64;
    const float* W = (t == 0 ? Wq : (t == 1 ? Wk : Wv)) + (size_t)h * DD * DHH;

    #pragma unroll
    for (int j = 0; j < 16; j++) {
        int lin = j * 256 + tid;
        int kk = lin >> 6, e = lin & 63;
        ts[kk][e] = W[(size_t)(k0 + kk) * DHH + e];
    }
    __syncthreads();
    #pragma unroll
    for (int j = 0; j < 16; j++) {
        int lin = j * 256 + tid;
        int e = lin >> 6, kk = lin & 63;
        float v = ts[kk][e];
        __nv_bfloat16 hi = __float2bfloat16(v);
        __nv_bfloat16 lo = __float2bfloat16(v - __bfloat162float(hi));
        size_t o = ((size_t)(t * 1024 + h * 64 + e)) * DD + k0 + kk;
        g_whi[o] = hi;
        g_wlo[o] = lo;
    }
}

// ============================================================
// QKV projection (unchanged — 71% of HMMA peak)
// ============================================================
#define T_AH 0u
#define T_AL 16384u
#define T_BH 32768u
#define T_BL 49152u
#define STAGE_BYTES 65536u

__device__ __forceinline__ void qkv_load_stage(uint32_t sb, int stage,
                                               int m0, int n0, int k0)
{
    const int tid = threadIdx.x;
    const char* pAh = (const char*)g_xhi;
    const char* pAl = (const char*)g_xlo;
    const char* pBh = (const char*)g_whi;
    const char* pBl = (const char*)g_wlo;
    uint32_t base = sb + stage * STAGE_BYTES;
    #pragma unroll
    for (int i = 0; i < 4; i++) {
        int chunk = tid + i * 256;
        int r = chunk >> 3;
        int c = chunk & 7;
        uint32_t off = r * 128 + (((uint32_t)(c ^ (r & 7))) << 4);
        size_t ga = ((size_t)(m0 + r) * DD + k0) * 2 + c * 16;
        size_t gb = ((size_t)(n0 + r) * DD + k0) * 2 + c * 16;
        CP16(base + T_AH + off, pAh + ga);
        CP16(base + T_AL + off, pAl + ga);
        CP16(base + T_BH + off, pBh + gb);
        CP16(base + T_BL + off, pBl + gb);
    }
}

__global__ __launch_bounds__(256) void qkv_mma_kernel(
    const float* __restrict__ bq, const float* __restrict__ bk,
    const float* __restrict__ bv)
{
    extern __shared__ char dsm[];
    const uint32_t sb = smem_u32(dsm);

    const int tid = threadIdx.x;
    const int wid = tid >> 5;
    const int lane = tid & 31;
    const int warp_m = wid >> 2;
    const int warp_n = wid & 3;
    const int n0 = blockIdx.x * 128;
    const int m0 = blockIdx.y * 128;

    float acc[4][4][4];
    #pragma unroll
    for (int i = 0; i < 4; i++)
        #pragma unroll
        for (int j = 0; j < 4; j++)
            #pragma unroll
            for (int v = 0; v < 4; v++) acc[i][j][v] = 0.f;

    qkv_load_stage(sb, 0, m0, n0, 0);
    CP_COMMIT();

    for (int kb = 0; kb < 16; kb++) {
        if (kb < 15) {
            qkv_load_stage(sb, (kb + 1) & 1, m0, n0, (kb + 1) * 64);
            CP_COMMIT();
            CP_WAIT1();
        } else {
            CP_WAIT0();
        }
        __syncthreads();

        const uint32_t stg = sb + (kb & 1) * STAGE_BYTES;
        #pragma unroll
        for (int s = 0; s < 4; s++) {
            uint32_t ah[16], al[16];
            #pragma unroll
            for (int mt = 0; mt < 4; mt++) {
                int r = warp_m * 64 + mt * 16 + (lane & 15);
                int c = 2 * s + (lane >> 4);
                uint32_t off = r * 128 + (((uint32_t)(c ^ (r & 7))) << 4);
                LDSM_X4(&ah[mt * 4], stg + T_AH + off);
                LDSM_X4(&al[mt * 4], stg + T_AL + off);
            }
            uint32_t bh[8], bl[8];
            #pragma unroll
            for (int bt = 0; bt < 2; bt++) {
                int nr = warp_n * 32 + bt * 16 + ((lane >> 4) << 3) + (lane & 7);
                int c = 2 * s + ((lane >> 3) & 1);
                uint32_t off = nr * 128 + (((uint32_t)(c ^ (nr & 7))) << 4);
                LDSM_X4(&bh[bt * 4], stg + T_BH + off);
                LDSM_X4(&bl[bt * 4], stg + T_BL + off);
            }
            #pragma unroll
            for (int mt = 0; mt < 4; mt++)
                #pragma unroll
                for (int nt = 0; nt < 4; nt++) {
                    int bi = (nt >> 1) * 4 + (nt & 1) * 2;
                    MMA16816(acc[mt][nt], &ah[mt * 4], &bh[bi]);
                }
            #pragma unroll
            for (int mt = 0; mt < 4; mt++)
                #pragma unroll
                for (int nt = 0; nt < 4; nt++) {
                    int bi = (nt >> 1) * 4 + (nt & 1) * 2;
                    MMA16816(acc[mt][nt], &ah[mt * 4], &bl[bi]);
                }
            #pragma unroll
            for (int mt = 0; mt < 4; mt++)
                #pragma unroll
                for (int nt = 0; nt < 4; nt++) {
                    int bi = (nt >> 1) * 4 + (nt & 1) * 2;
                    MMA16816(acc[mt][nt], &al[mt * 4], &bh[bi]);
                }
        }
        __syncthreads();
    }

    #pragma unroll
    for (int nt = 0; nt < 4; nt++) {
        int n = n0 + warp_n * 32 + nt * 8 + (lane & 3) * 2;
        int t = n >> 10;
        int h = (n >> 6) & 15;
        int e = n & 63;
        const float* bias = (t == 0 ? bq : (t == 1 ? bk : bv));
        __nv_bfloat16* dhi = (t == 0 ? g_qhi : (t == 1 ? g_khi : g_vhi));
        __nv_bfloat16* dlo = (t == 0 ? g_qlo : (t == 1 ? g_klo : g_vlo));
        float b0v = bias[h * 64 + e];
        float b1v = bias[h * 64 + e + 1];
        #pragma unroll
        for (int mt = 0; mt < 4; mt++) {
            #pragma unroll
            for (int half = 0; half < 2; half++) {
                int row = m0 + warp_m * 64 + mt * 16 + (lane >> 2) + half * 8;
                int b = row >> 10;
                int s = row & 1023;
                int bh = b * HH + h;
                float v0 = acc[mt][nt][half * 2]     + b0v;
                float v1 = acc[mt][nt][half * 2 + 1] + b1v;
                __nv_bfloat16 h0 = __float2bfloat16(v0);
                __nv_bfloat16 h1 = __float2bfloat16(v1);
                __nv_bfloat16 l0 = __float2bfloat16(v0 - __bfloat162float(h0));
                __nv_bfloat16 l1 = __float2bfloat16(v1 - __bfloat162float(h1));
                size_t o = ((size_t)(bh << 10) + s) * 64 + e;
                *(__nv_bfloat162*)&dhi[o] = __nv_bfloat162(h0, h1);
                *(__nv_bfloat162*)&dlo[o] = __nv_bfloat162(l0, l1);
            }
        }
    }
}

// ============================================================
// Flash attention: 128-thread CTAs (4 warps, 64 q-rows), KT=64,
// 2 stages, 80KB smem -> 2 CTAs/SM (validated -18us in R11).
// ============================================================
#define AST    0u
#define AST_SZ 32768u
#define AQ_H   65536u
#define AQ_L   73728u

__device__ __forceinline__ void attn_load_kv(uint32_t stg, int bh, int k0)
{
    const int tid = threadIdx.x;
    const char* kh = (const char*)g_khi;
    const char* kl = (const char*)g_klo;
    const char* vh = (const char*)g_vhi;
    const char* vl = (const char*)g_vlo;
    #pragma unroll
    for (int i = 0; i < 4; i++) {
        int ch = i * 128 + tid;
        int r = ch >> 3;
        int c = ch & 7;
        uint32_t off = r * 128 + (((uint32_t)(c ^ (r & 7))) << 4);
        size_t src = ((size_t)((bh << 10) + k0 + r)) * 128 + c * 16;
        CP16(stg + 0 + off, kh + src);
        CP16(stg + 8192 + off, kl + src);
        CP16(stg + 16384 + off, vh + src);
        CP16(stg + 24576 + off, vl + src);
    }
}

__global__ __launch_bounds__(128) void attn_mma_kernel()
{
    extern __shared__ char dsm[];
    const uint32_t sb = smem_u32(dsm);

    const int tid = threadIdx.x;
    const int wid = tid >> 5;
    const int lane = tid & 31;
    const int qt = 15 - blockIdx.x;
    const int bh = blockIdx.y;
    const int q0 = qt * 64;
    const int n_kt = qt + 1;

    {
        const char* qh = (const char*)g_qhi;
        const char* ql = (const char*)g_qlo;
        #pragma unroll
        for (int i = 0; i < 4; i++) {
            int ch = i * 128 + tid;
            int r = ch >> 3;
            int c = ch & 7;
            uint32_t off = r * 128 + (((uint32_t)(c ^ (r & 7))) << 4);
            size_t src = ((size_t)((bh << 10) + q0 + r)) * 128 + c * 16;
            CP16(sb + AQ_H + off, qh + src);
            CP16(sb + AQ_L + off, ql + src);
        }
        attn_load_kv(sb + AST, bh, 0);
        CP_COMMIT();
    }

    float o[8][4];
    #pragma unroll
    for (int i = 0; i < 8; i++)
        #pragma unroll
        for (int j = 0; j < 4; j++) o[i][j] = 0.f;
    float m[2] = {-1e30f, -1e30f};
    float l[2] = {0.f, 0.f};
    uint32_t qfh[16], qfl[16];
    const int wr0 = q0 + wid * 16;

    for (int kt = 0; kt < n_kt; kt++) {
        if (kt + 1 < n_kt) {
            attn_load_kv(sb + AST + ((kt + 1) & 1) * AST_SZ, bh, (kt + 1) * 64);
            CP_COMMIT();
            CP_WAIT1();
        } else {
            CP_WAIT0();
        }
        __syncthreads();

        if (kt == 0) {
            #pragma unroll
            for (int ks = 0; ks < 4; ks++) {
                int r = wid * 16 + (lane & 15);
                int c = 2 * ks + (lane >> 4);
                uint32_t off = r * 128 + (((uint32_t)(c ^ (r & 7))) << 4);
                LDSM_X4(&qfh[ks * 4], sb + AQ_H + off);
                LDSM_X4(&qfl[ks * 4], sb + AQ_L + off);
            }
        }

        const int k0 = kt * 64;
        const uint32_t stg = sb + AST + (kt & 1) * AST_SZ;

        // ---- S = Q K^T (product-major) ----
        float sc[8][4];
        #pragma unroll
        for (int i = 0; i < 8; i++)
            #pragma unroll
            for (int j = 0; j < 4; j++) sc[i][j] = 0.f;
        #pragma unroll
        for (int ks = 0; ks < 4; ks++) {
            uint32_t kfh[16], kfl[16];
            #pragma unroll
            for (int nt2 = 0; nt2 < 4; nt2++) {
                int nr = nt2 * 16 + ((lane >> 4) << 3) + (lane & 7);
                int c = 2 * ks + ((lane >> 3) & 1);
                uint32_t off = nr * 128 + (((uint32_t)(c ^ (nr & 7))) << 4);
                LDSM_X4(&kfh[nt2 * 4], stg + 0 + off);
                LDSM_X4(&kfl[nt2 * 4], stg + 8192 + off);
            }
            #pragma unroll
            for (int nt = 0; nt < 8; nt++) {
                int bi = (nt >> 1) * 4 + (nt & 1) * 2;
                MMA16816(sc[nt], &qfh[ks * 4], &kfh[bi]);
            }
            #pragma unroll
            for (int nt = 0; nt < 8; nt++) {
                int bi = (nt >> 1) * 4 + (nt & 1) * 2;
                MMA16816(sc[nt], &qfh[ks * 4], &kfl[bi]);
            }
            #pragma unroll
            for (int nt = 0; nt < 8; nt++) {
                int bi = (nt >> 1) * 4 + (nt & 1) * 2;
                MMA16816(sc[nt], &qfl[ks * 4], &kfh[bi]);
            }
        }
        // ---- online softmax over 64 cols ----
        const bool need_mask = (k0 + 63 > wr0);
        uint32_t ph[16], pl[16];
        float alpha[2];
        #pragma unroll
        for (int rs = 0; rs < 2; rs++) {
            int grow = wr0 + (lane >> 2) + rs * 8;
            float mx = -1e30f;
            #pragma unroll
            for (int nt = 0; nt < 8; nt++) {
                float v0 = sc[nt][rs * 2] * 0.125f;
                float v1 = sc[nt][rs * 2 + 1] * 0.125f;
                if (need_mask) {
                    int gc = k0 + nt * 8 + 2 * (lane & 3);
                    if (gc > grow) v0 = -1e30f;
                    if (gc + 1 > grow) v1 = -1e30f;
                }
                sc[nt][rs * 2] = v0;
                sc[nt][rs * 2 + 1] = v1;
                mx = fmaxf(mx, fmaxf(v0, v1));
            }
            mx = fmaxf(mx, __shfl_xor_sync(0xffffffffu, mx, 1));
            mx = fmaxf(mx, __shfl_xor_sync(0xffffffffu, mx, 2));
            float mn = fmaxf(m[rs], mx);
            alpha[rs] = __expf(m[rs] - mn);
            m[rs] = mn;
            float rsum = 0.f;
            #pragma unroll
            for (int nt = 0; nt < 8; nt++) {
                float p0 = __expf(sc[nt][rs * 2] - mn);
                float p1 = __expf(sc[nt][rs * 2 + 1] - mn);
                rsum += p0 + p1;
                uint32_t hp = pack_bf16x2(p0, p1);
                float r0 = p0 - __uint_as_float(hp << 16);
                float r1 = p1 - __uint_as_float(hp & 0xFFFF0000u);
                uint32_t lp = pack_bf16x2(r0, r1);
                int idx = (nt >> 1) * 4 + (nt & 1) * 2 + rs;
                ph[idx] = hp;
                pl[idx] = lp;
            }
            rsum += __shfl_xor_sync(0xffffffffu, rsum, 1);
            rsum += __shfl_xor_sync(0xffffffffu, rsum, 2);
            l[rs] = l[rs] * alpha[rs] + rsum;
            #pragma unroll
            for (int ne = 0; ne < 8; ne++) {
                o[ne][rs * 2] *= alpha[rs];
                o[ne][rs * 2 + 1] *= alpha[rs];
            }
        }
        // ---- O += P V (V via trans-ldmatrix, product-major) ----
        #pragma unroll
        for (int kp = 0; kp < 4; kp++) {
            uint32_t vfh[16], vfl[16];
            #pragma unroll
            for (int ne2 = 0; ne2 < 4; ne2++) {
                int r = kp * 16 + (lane & 15);
                int c = ne2 * 2 + (lane >> 4);
                uint32_t off = r * 128 + (((uint32_t)(c ^ (r & 7))) << 4);
                LDSM_X4_T(&vfh[ne2 * 4], stg + 16384 + off);
                LDSM_X4_T(&vfl[ne2 * 4], stg + 24576 + off);
            }
            #pragma unroll
            for (int ne = 0; ne < 8; ne++) {
                int bi = (ne >> 1) * 4 + (ne & 1) * 2;
                MMA16816(o[ne], &ph[kp * 4], &vfh[bi]);
            }
            #pragma unroll
            for (int ne = 0; ne < 8; ne++) {
                int bi = (ne >> 1) * 4 + (ne & 1) * 2;
                MMA16816(o[ne], &ph[kp * 4], &vfl[bi]);
            }
            #pragma unroll
            for (int ne = 0; ne < 8; ne++) {
                int bi = (ne >> 1) * 4 + (ne & 1) * 2;
                MMA16816(o[ne], &pl[kp * 4], &vfh[bi]);
            }
        }
        __syncthreads();
    }

    // ---- normalize + write ----
    #pragma unroll
    for (int rs = 0; rs < 2; rs++) {
        float inv = 1.f / l[rs];
        int row = wr0 + (lane >> 2) + rs * 8;
        #pragma unroll
        for (int ne = 0; ne < 8; ne++) {
            int e = ne * 8 + 2 * (lane & 3);
            float2 r2;
            r2.x = o[ne][rs * 2] * inv;
            r2.y = o[ne][rs * 2 + 1] * inv;
            *(float2*)&g_z[((size_t)(bh << 10) + row) * 64 + e] = r2;
        }
    }
}

// ============================================================
// FF with fused head-sum (reverted to proven 4-tokens/CTA shape)
// ============================================================
__device__ __forceinline__ float gelu_exact(float v)
{
    return 0.5f * v * (1.0f + erff(v * 0.70710678118654752f));
}

__global__ __launch_bounds__(256) void ff_kernel(const float* __restrict__ Wf,
                                                 const float* __restrict__ bf,
                                                 float* __restrict__ out)
{
    __shared__ float ssum[4][64];
    const int t0 = blockIdx.x * 4;
    const int tid = threadIdx.x;

    {
        int t = tid >> 6;
        int e = tid & 63;
        int tok = t0 + t;
        int b = tok >> 10;
        int s = tok & 1023;
        const float* zp = g_z + ((size_t)(b * HH) * SS + s) * DHH + e;
        float acc = 0.f;
        #pragma unroll
        for (int h = 0; h < HH; h++) acc += zp[(size_t)h * SS * DHH];
        ssum[t][e] = acc;
    }
    __syncthreads();

    const int col = tid * 4;
    float acc[4][4];
    #pragma unroll
    for (int t = 0; t < 4; t++)
        #pragma unroll
        for (int j = 0; j < 4; j++) acc[t][j] = 0.f;

    #pragma unroll 8
    for (int e = 0; e < 64; e++) {
        float4 w = *(const float4*)&Wf[(size_t)e * DD + col];
        #pragma unroll
        for (int t = 0; t < 4; t++) {
            float sv = ssum[t][e];
            acc[t][0] += sv * w.x;
            acc[t][1] += sv * w.y;
            acc[t][2] += sv * w.z;
            acc[t][3] += sv * w.w;
        }
    }

    float4 b4 = *(const float4*)&bf[col];
    #pragma unroll
    for (int t = 0; t < 4; t++) {
        float4 r;
        r.x = gelu_exact(acc[t][0] + b4.x);
        r.y = gelu_exact(acc[t][1] + b4.y);
        r.z = gelu_exact(acc[t][2] + b4.z);
        r.w = gelu_exact(acc[t][3] + b4.w);
        *(float4*)&out[(size_t)(t0 + t) * DD + col] = r;
    }
}

// ============================================================
extern "C" void kernel_launch(void* const* d_in, const int* in_sizes, int n_in,
                              void* d_out, int out_size)
{
    const float* x  = (const float*)d_in[0];
    const float* Wq = (const float*)d_in[1];
    const float* bq = (const float*)d_in[2];
    const float* Wk = (const float*)d_in[3];
    const float* bk = (const float*)d_in[4];
    const float* Wv = (const float*)d_in[5];
    const float* bv = (const float*)d_in[6];
    const float* Wf = (const float*)d_in[7];
    const float* bf = (const float*)d_in[8];
    float* out = (float*)d_out;

    static const int QKV_SMEM = 131072;   // 2 stages x 64KB
    static const int ATT_SMEM = 81920;    // 2 stages x 32KB + Q 16KB
    cudaFuncSetAttribute(qkv_mma_kernel,
                         cudaFuncAttributeMaxDynamicSharedMemorySize, QKV_SMEM);
    cudaFuncSetAttribute(attn_mma_kernel,
                         cudaFuncAttributeMaxDynamicSharedMemorySize, ATT_SMEM);

    split_all_kernel<<<4096 + 768, 256>>>(x, Wq, Wk, Wv);

    dim3 gMMA(NFLAT / 128, (BB * SS) / 128);
    qkv_mma_kernel<<<gMMA, 256, QKV_SMEM>>>(bq, bk, bv);

    dim3 gAtt(16, 64);
    attn_mma_kernel<<<gAtt, 128, ATT_SMEM>>>();

    ff_kernel<<<(BB * SS) / 4, 256>>>(Wf, bf, out);
}

// round 14
// speedup vs baseline: 1.4997x; 1.4124x over previous
#include <cuda_runtime.h>
#include <cuda_fp16.h>
#include <math.h>
#include <stdint.h>

#define BB  4
#define SS  1024
#define DD  1024
#define HH  16
#define DHH 64
#define NFLAT 3072   // q:0-1023, k:1024-2047, v:2048-3071

// ---- persistent scratch (no allocations allowed) ----
__device__ float g_z[BB*HH*SS*DHH];     // per-head attention output

__device__ __half g_xh[BB*SS*DD];       // x as single fp16 (A operand)
__device__ __half g_whi[NFLAT*DD];      // W transposed [n][k], fp16 hi
__device__ __half g_wlo[NFLAT*DD];      // fp16 lo

// attention operands, [bh][s][e]
__device__ __half g_q[64*SS*DHH];       // Q single fp16
__device__ __half g_khi[64*SS*DHH];
__device__ __half g_klo[64*SS*DHH];
__device__ __half g_vhi[64*SS*DHH];
__device__ __half g_vlo[64*SS*DHH];

// ============================================================
// helpers
// ============================================================
__device__ __forceinline__ uint32_t smem_u32(const void* p) {
    uint32_t a;
    asm("{ .reg .u64 t; cvta.to.shared.u64 t, %1; cvt.u32.u64 %0, t; }"
        : "=r"(a) : "l"(p));
    return a;
}

#define CP16(dst, src) \
    asm volatile("cp.async.cg.shared.global [%0], [%1], 16;" \
                 :: "r"(dst), "l"(src) : "memory")
#define CP_COMMIT() asm volatile("cp.async.commit_group;" ::: "memory")
#define CP_WAIT1()  asm volatile("cp.async.wait_group 1;" ::: "memory")
#define CP_WAIT0()  asm volatile("cp.async.wait_group 0;" ::: "memory")

#define LDSM_X4(R, addr) \
    asm volatile("ldmatrix.sync.aligned.m8n8.x4.shared.b16 {%0,%1,%2,%3}, [%4];" \
                 : "=r"((R)[0]), "=r"((R)[1]), "=r"((R)[2]), "=r"((R)[3]) \
                 : "r"(addr))

#define LDSM_X4_T(R, addr) \
    asm volatile("ldmatrix.sync.aligned.m8n8.x4.trans.shared.b16 {%0,%1,%2,%3}, [%4];" \
                 : "=r"((R)[0]), "=r"((R)[1]), "=r"((R)[2]), "=r"((R)[3]) \
                 : "r"(addr))

#define MMAF16(D, A, B) \
    asm volatile("mma.sync.aligned.m16n8k16.row.col.f32.f16.f16.f32 " \
                 "{%0,%1,%2,%3}, {%4,%5,%6,%7}, {%8,%9}, {%0,%1,%2,%3};" \
                 : "+f"((D)[0]), "+f"((D)[1]), "+f"((D)[2]), "+f"((D)[3]) \
                 : "r"((A)[0]), "r"((A)[1]), "r"((A)[2]), "r"((A)[3]), \
                   "r"((B)[0]), "r"((B)[1]))

// pack two f32 -> f16x2 reg: lo = a, hi = b
__device__ __forceinline__ uint32_t pack_h16x2(float a, float b) {
    uint32_t r;
    asm("cvt.rn.f16x2.f32 %0, %1, %2;" : "=r"(r) : "f"(b), "f"(a));
    return r;
}

// ============================================================
// Fused split kernel:
//   blocks [0, 4096)    : x -> g_xh (single fp16)
//   blocks [4096, 4864) : W transpose + fp16 hi/lo -> g_whi/g_wlo
// ============================================================
__global__ __launch_bounds__(256) void split_all_kernel(
    const float* __restrict__ x,
    const float* __restrict__ Wq, const float* __restrict__ Wk,
    const float* __restrict__ Wv)
{
    const int tid = threadIdx.x;
    if (blockIdx.x < 4096) {
        int i4 = blockIdx.x * 256 + tid;
        float4 v = ((const float4*)x)[i4];
        __half2* ph = (__half2*)g_xh;
        ph[i4 * 2]     = __half2(__float2half_rn(v.x), __float2half_rn(v.y));
        ph[i4 * 2 + 1] = __half2(__float2half_rn(v.z), __float2half_rn(v.w));
        return;
    }
    __shared__ float ts[64][65];
    const int bid = blockIdx.x - 4096;
    const int hf = bid >> 4;
    const int kc = bid & 15;
    const int t = hf >> 4;
    const int h = hf & 15;
    const int k0 = kc * 64;
    const float* W = (t == 0 ? Wq : (t == 1 ? Wk : Wv)) + (size_t)h * DD * DHH;

    #pragma unroll
    for (int j = 0; j < 16; j++) {
        int lin = j * 256 + tid;
        int kk = lin >> 6, e = lin & 63;
        ts[kk][e] = W[(size_t)(k0 + kk) * DHH + e];
    }
    __syncthreads();
    #pragma unroll
    for (int j = 0; j < 16; j++) {
        int lin = j * 256 + tid;
        int e = lin >> 6, kk = lin & 63;
        float v = ts[kk][e];
        __half hi = __float2half_rn(v);
        __half lo = __float2half_rn(v - __half2float(hi));
        size_t o = ((size_t)(t * 1024 + h * 64 + e)) * DD + k0 + kk;
        g_whi[o] = hi;
        g_wlo[o] = lo;
    }
}

// ============================================================
// QKV projection, fp16 2-product: acc = A_h*B_h + A_h*B_l.
// BK=64, 2 stages; stage = A 16KB + BH 16KB + BL 16KB = 48KB.
// ============================================================
#define T_A  0u
#define T_BH 16384u
#define T_BL 32768u
#define STAGE_BYTES 49152u

__device__ __forceinline__ void qkv_load_stage(uint32_t sb, int stage,
                                               int m0, int n0, int k0)
{
    const int tid = threadIdx.x;
    const char* pA  = (const char*)g_xh;
    const char* pBh = (const char*)g_whi;
    const char* pBl = (const char*)g_wlo;
    uint32_t base = sb + stage * STAGE_BYTES;
    #pragma unroll
    for (int i = 0; i < 4; i++) {
        int chunk = tid + i * 256;            // 0..1023
        int r = chunk >> 3;
        int c = chunk & 7;
        uint32_t off = r * 128 + (((uint32_t)(c ^ (r & 7))) << 4);
        size_t ga = ((size_t)(m0 + r) * DD + k0) * 2 + c * 16;
        size_t gb = ((size_t)(n0 + r) * DD + k0) * 2 + c * 16;
        CP16(base + T_A + off, pA + ga);
        CP16(base + T_BH + off, pBh + gb);
        CP16(base + T_BL + off, pBl + gb);
    }
}

__global__ __launch_bounds__(256) void qkv_mma_kernel(
    const float* __restrict__ bq, const float* __restrict__ bk,
    const float* __restrict__ bv)
{
    extern __shared__ char dsm[];
    const uint32_t sb = smem_u32(dsm);

    const int tid = threadIdx.x;
    const int wid = tid >> 5;
    const int lane = tid & 31;
    const int warp_m = wid >> 2;
    const int warp_n = wid & 3;
    const int n0 = blockIdx.x * 128;
    const int m0 = blockIdx.y * 128;

    float acc[4][4][4];
    #pragma unroll
    for (int i = 0; i < 4; i++)
        #pragma unroll
        for (int j = 0; j < 4; j++)
            #pragma unroll
            for (int v = 0; v < 4; v++) acc[i][j][v] = 0.f;

    qkv_load_stage(sb, 0, m0, n0, 0);
    CP_COMMIT();

    for (int kb = 0; kb < 16; kb++) {
        if (kb < 15) {
            qkv_load_stage(sb, (kb + 1) & 1, m0, n0, (kb + 1) * 64);
            CP_COMMIT();
            CP_WAIT1();
        } else {
            CP_WAIT0();
        }
        __syncthreads();

        const uint32_t stg = sb + (kb & 1) * STAGE_BYTES;
        #pragma unroll
        for (int s = 0; s < 4; s++) {
            uint32_t ah[16];
            #pragma unroll
            for (int mt = 0; mt < 4; mt++) {
                int r = warp_m * 64 + mt * 16 + (lane & 15);
                int c = 2 * s + (lane >> 4);
                uint32_t off = r * 128 + (((uint32_t)(c ^ (r & 7))) << 4);
                LDSM_X4(&ah[mt * 4], stg + T_A + off);
            }
            uint32_t bh[8], bl[8];
            #pragma unroll
            for (int bt = 0; bt < 2; bt++) {
                int nr = warp_n * 32 + bt * 16 + ((lane >> 4) << 3) + (lane & 7);
                int c = 2 * s + ((lane >> 3) & 1);
                uint32_t off = nr * 128 + (((uint32_t)(c ^ (nr & 7))) << 4);
                LDSM_X4(&bh[bt * 4], stg + T_BH + off);
                LDSM_X4(&bl[bt * 4], stg + T_BL + off);
            }
            #pragma unroll
            for (int mt = 0; mt < 4; mt++)
                #pragma unroll
                for (int nt = 0; nt < 4; nt++) {
                    int bi = (nt >> 1) * 4 + (nt & 1) * 2;
                    MMAF16(acc[mt][nt], &ah[mt * 4], &bh[bi]);
                }
            #pragma unroll
            for (int mt = 0; mt < 4; mt++)
                #pragma unroll
                for (int nt = 0; nt < 4; nt++) {
                    int bi = (nt >> 1) * 4 + (nt & 1) * 2;
                    MMAF16(acc[mt][nt], &ah[mt * 4], &bl[bi]);
                }
        }
        __syncthreads();
    }

    // ---- epilogue: bias; q single fp16, k/v hi/lo fp16 ----
    #pragma unroll
    for (int nt = 0; nt < 4; nt++) {
        int n = n0 + warp_n * 32 + nt * 8 + (lane & 3) * 2;
        int t = n >> 10;
        int h = (n >> 6) & 15;
        int e = n & 63;
        const float* bias = (t == 0 ? bq : (t == 1 ? bk : bv));
        float b0v = bias[h * 64 + e];
        float b1v = bias[h * 64 + e + 1];
        #pragma unroll
        for (int mt = 0; mt < 4; mt++) {
            #pragma unroll
            for (int half = 0; half < 2; half++) {
                int row = m0 + warp_m * 64 + mt * 16 + (lane >> 2) + half * 8;
                int b = row >> 10;
                int s = row & 1023;
                int bh = b * HH + h;
                float v0 = acc[mt][nt][half * 2]     + b0v;
                float v1 = acc[mt][nt][half * 2 + 1] + b1v;
                __half h0 = __float2half_rn(v0);
                __half h1 = __float2half_rn(v1);
                size_t o = ((size_t)(bh << 10) + s) * 64 + e;
                if (t == 0) {
                    *(__half2*)&g_q[o] = __half2(h0, h1);
                } else {
                    __half l0 = __float2half_rn(v0 - __half2float(h0));
                    __half l1 = __float2half_rn(v1 - __half2float(h1));
                    __half* dhi = (t == 1 ? g_khi : g_vhi);
                    __half* dlo = (t == 1 ? g_klo : g_vlo);
                    *(__half2*)&dhi[o] = __half2(h0, h1);
                    *(__half2*)&dlo[o] = __half2(l0, l1);
                }
            }
        }
    }
}

// ============================================================
// Flash attention, fp16 2-product: S = Qh*Kh + Qh*Kl; O += Ph*Vh + Ph*Vl.
// 128-thread CTAs (4 warps, 64 q-rows), KT=64, 2 stages.
// stage: KH 0, KL 8K, VH 16K, VL 24K (32KB); Q single at 64K (8KB). 72KB.
// ============================================================
#define AST    0u
#define AST_SZ 32768u
#define AQ     65536u

__device__ __forceinline__ void attn_load_kv(uint32_t stg, int bh, int k0)
{
    const int tid = threadIdx.x;
    const char* kh = (const char*)g_khi;
    const char* kl = (const char*)g_klo;
    const char* vh = (const char*)g_vhi;
    const char* vl = (const char*)g_vlo;
    #pragma unroll
    for (int i = 0; i < 4; i++) {
        int ch = i * 128 + tid;        // 0..511
        int r = ch >> 3;               // 0..63
        int c = ch & 7;
        uint32_t off = r * 128 + (((uint32_t)(c ^ (r & 7))) << 4);
        size_t src = ((size_t)((bh << 10) + k0 + r)) * 128 + c * 16;
        CP16(stg + 0 + off, kh + src);
        CP16(stg + 8192 + off, kl + src);
        CP16(stg + 16384 + off, vh + src);
        CP16(stg + 24576 + off, vl + src);
    }
}

__global__ __launch_bounds__(128) void attn_mma_kernel()
{
    extern __shared__ char dsm[];
    const uint32_t sb = smem_u32(dsm);

    const int tid = threadIdx.x;
    const int wid = tid >> 5;
    const int lane = tid & 31;
    const int qt = 15 - blockIdx.x;
    const int bh = blockIdx.y;
    const int q0 = qt * 64;
    const int n_kt = qt + 1;

    {
        const char* qp = (const char*)g_q;
        #pragma unroll
        for (int i = 0; i < 4; i++) {
            int ch = i * 128 + tid;    // 0..511
            int r = ch >> 3;           // 0..63
            int c = ch & 7;
            uint32_t off = r * 128 + (((uint32_t)(c ^ (r & 7))) << 4);
            size_t src = ((size_t)((bh << 10) + q0 + r)) * 128 + c * 16;
            CP16(sb + AQ + off, qp + src);
        }
        attn_load_kv(sb + AST, bh, 0);
        CP_COMMIT();
    }

    float o[8][4];
    #pragma unroll
    for (int i = 0; i < 8; i++)
        #pragma unroll
        for (int j = 0; j < 4; j++) o[i][j] = 0.f;
    float m[2] = {-1e30f, -1e30f};
    float l[2] = {0.f, 0.f};
    uint32_t qf[16];
    const int wr0 = q0 + wid * 16;

    for (int kt = 0; kt < n_kt; kt++) {
        if (kt + 1 < n_kt) {
            attn_load_kv(sb + AST + ((kt + 1) & 1) * AST_SZ, bh, (kt + 1) * 64);
            CP_COMMIT();
            CP_WAIT1();
        } else {
            CP_WAIT0();
        }
        __syncthreads();

        if (kt == 0) {
            #pragma unroll
            for (int ks = 0; ks < 4; ks++) {
                int r = wid * 16 + (lane & 15);
                int c = 2 * ks + (lane >> 4);
                uint32_t off = r * 128 + (((uint32_t)(c ^ (r & 7))) << 4);
                LDSM_X4(&qf[ks * 4], sb + AQ + off);
            }
        }

        const int k0 = kt * 64;
        const uint32_t stg = sb + AST + (kt & 1) * AST_SZ;

        // ---- S = Q K^T (2 products, product-major) ----
        float sc[8][4];
        #pragma unroll
        for (int i = 0; i < 8; i++)
            #pragma unroll
            for (int j = 0; j < 4; j++) sc[i][j] = 0.f;
        #pragma unroll
        for (int ks = 0; ks < 4; ks++) {
            uint32_t kfh[16], kfl[16];
            #pragma unroll
            for (int nt2 = 0; nt2 < 4; nt2++) {
                int nr = nt2 * 16 + ((lane >> 4) << 3) + (lane & 7);
                int c = 2 * ks + ((lane >> 3) & 1);
                uint32_t off = nr * 128 + (((uint32_t)(c ^ (nr & 7))) << 4);
                LDSM_X4(&kfh[nt2 * 4], stg + 0 + off);
                LDSM_X4(&kfl[nt2 * 4], stg + 8192 + off);
            }
            #pragma unroll
            for (int nt = 0; nt < 8; nt++) {
                int bi = (nt >> 1) * 4 + (nt & 1) * 2;
                MMAF16(sc[nt], &qf[ks * 4], &kfh[bi]);
            }
            #pragma unroll
            for (int nt = 0; nt < 8; nt++) {
                int bi = (nt >> 1) * 4 + (nt & 1) * 2;
                MMAF16(sc[nt], &qf[ks * 4], &kfl[bi]);
            }
        }
        // ---- online softmax over 64 cols; P as single fp16 ----
        const bool need_mask = (k0 + 63 > wr0);
        uint32_t ph[16];
        float alpha[2];
        #pragma unroll
        for (int rs = 0; rs < 2; rs++) {
            int grow = wr0 + (lane >> 2) + rs * 8;
            float mx = -1e30f;
            #pragma unroll
            for (int nt = 0; nt < 8; nt++) {
                float v0 = sc[nt][rs * 2] * 0.125f;
                float v1 = sc[nt][rs * 2 + 1] * 0.125f;
                if (need_mask) {
                    int gc = k0 + nt * 8 + 2 * (lane & 3);
                    if (gc > grow) v0 = -1e30f;
                    if (gc + 1 > grow) v1 = -1e30f;
                }
                sc[nt][rs * 2] = v0;
                sc[nt][rs * 2 + 1] = v1;
                mx = fmaxf(mx, fmaxf(v0, v1));
            }
            mx = fmaxf(mx, __shfl_xor_sync(0xffffffffu, mx, 1));
            mx = fmaxf(mx, __shfl_xor_sync(0xffffffffu, mx, 2));
            float mn = fmaxf(m[rs], mx);
            alpha[rs] = __expf(m[rs] - mn);
            m[rs] = mn;
            float rsum = 0.f;
            #pragma unroll
            for (int nt = 0; nt < 8; nt++) {
                float p0 = __expf(sc[nt][rs * 2] - mn);
                float p1 = __expf(sc[nt][rs * 2 + 1] - mn);
                rsum += p0 + p1;
                int idx = (nt >> 1) * 4 + (nt & 1) * 2 + rs;
                ph[idx] = pack_h16x2(p0, p1);
            }
            rsum += __shfl_xor_sync(0xffffffffu, rsum, 1);
            rsum += __shfl_xor_sync(0xffffffffu, rsum, 2);
            l[rs] = l[rs] * alpha[rs] + rsum;
            #pragma unroll
            for (int ne = 0; ne < 8; ne++) {
                o[ne][rs * 2] *= alpha[rs];
                o[ne][rs * 2 + 1] *= alpha[rs];
            }
        }
        // ---- O += P V (2 products, V via trans-ldmatrix) ----
        #pragma unroll
        for (int kp = 0; kp < 4; kp++) {
            uint32_t vfh[16], vfl[16];
            #pragma unroll
            for (int ne2 = 0; ne2 < 4; ne2++) {
                int r = kp * 16 + (lane & 15);
                int c = ne2 * 2 + (lane >> 4);
                uint32_t off = r * 128 + (((uint32_t)(c ^ (r & 7))) << 4);
                LDSM_X4_T(&vfh[ne2 * 4], stg + 16384 + off);
                LDSM_X4_T(&vfl[ne2 * 4], stg + 24576 + off);
            }
            #pragma unroll
            for (int ne = 0; ne < 8; ne++) {
                int bi = (ne >> 1) * 4 + (ne & 1) * 2;
                MMAF16(o[ne], &ph[kp * 4], &vfh[bi]);
            }
            #pragma unroll
            for (int ne = 0; ne < 8; ne++) {
                int bi = (ne >> 1) * 4 + (ne & 1) * 2;
                MMAF16(o[ne], &ph[kp * 4], &vfl[bi]);
            }
        }
        __syncthreads();
    }

    // ---- normalize + write ----
    #pragma unroll
    for (int rs = 0; rs < 2; rs++) {
        float inv = 1.f / l[rs];
        int row = wr0 + (lane >> 2) + rs * 8;
        #pragma unroll
        for (int ne = 0; ne < 8; ne++) {
            int e = ne * 8 + 2 * (lane & 3);
            float2 r2;
            r2.x = o[ne][rs * 2] * inv;
            r2.y = o[ne][rs * 2 + 1] * inv;
            *(float2*)&g_z[((size_t)(bh << 10) + row) * 64 + e] = r2;
        }
    }
}

// ============================================================
// FF with fused head-sum (proven 4-tokens/CTA shape)
// ============================================================
__device__ __forceinline__ float gelu_exact(float v)
{
    return 0.5f * v * (1.0f + erff(v * 0.70710678118654752f));
}

__global__ __launch_bounds__(256) void ff_kernel(const float* __restrict__ Wf,
                                                 const float* __restrict__ bf,
                                                 float* __restrict__ out)
{
    __shared__ float ssum[4][64];
    const int t0 = blockIdx.x * 4;
    const int tid = threadIdx.x;

    {
        int t = tid >> 6;
        int e = tid & 63;
        int tok = t0 + t;
        int b = tok >> 10;
        int s = tok & 1023;
        const float* zp = g_z + ((size_t)(b * HH) * SS + s) * DHH + e;
        float acc = 0.f;
        #pragma unroll
        for (int h = 0; h < HH; h++) acc += zp[(size_t)h * SS * DHH];
        ssum[t][e] = acc;
    }
    __syncthreads();

    const int col = tid * 4;
    float acc[4][4];
    #pragma unroll
    for (int t = 0; t < 4; t++)
        #pragma unroll
        for (int j = 0; j < 4; j++) acc[t][j] = 0.f;

    #pragma unroll 8
    for (int e = 0; e < 64; e++) {
        float4 w = *(const float4*)&Wf[(size_t)e * DD + col];
        #pragma unroll
        for (int t = 0; t < 4; t++) {
            float sv = ssum[t][e];
            acc[t][0] += sv * w.x;
            acc[t][1] += sv * w.y;
            acc[t][2] += sv * w.z;
            acc[t][3] += sv * w.w;
        }
    }

    float4 b4 = *(const float4*)&bf[col];
    #pragma unroll
    for (int t = 0; t < 4; t++) {
        float4 r;
        r.x = gelu_exact(acc[t][0] + b4.x);
        r.y = gelu_exact(acc[t][1] + b4.y);
        r.z = gelu_exact(acc[t][2] + b4.z);
        r.w = gelu_exact(acc[t][3] + b4.w);
        *(float4*)&out[(size_t)(t0 + t) * DD + col] = r;
    }
}

// ============================================================
extern "C" void kernel_launch(void* const* d_in, const int* in_sizes, int n_in,
                              void* d_out, int out_size)
{
    const float* x  = (const float*)d_in[0];
    const float* Wq = (const float*)d_in[1];
    const float* bq = (const float*)d_in[2];
    const float* Wk = (const float*)d_in[3];
    const float* bk = (const float*)d_in[4];
    const float* Wv = (const float*)d_in[5];
    const float* bv = (const float*)d_in[6];
    const float* Wf = (const float*)d_in[7];
    const float* bf = (const float*)d_in[8];
    float* out = (float*)d_out;

    static const int QKV_SMEM = 98304;    // 2 stages x 48KB
    static const int ATT_SMEM = 73728;    // 2 stages x 32KB + Q 8KB
    cudaFuncSetAttribute(qkv_mma_kernel,
                         cudaFuncAttributeMaxDynamicSharedMemorySize, QKV_SMEM);
    cudaFuncSetAttribute(attn_mma_kernel,
                         cudaFuncAttributeMaxDynamicSharedMemorySize, ATT_SMEM);

    split_all_kernel<<<4096 + 768, 256>>>(x, Wq, Wk, Wv);

    dim3 gMMA(NFLAT / 128, (BB * SS) / 128);
    qkv_mma_kernel<<<gMMA, 256, QKV_SMEM>>>(bq, bk, bv);

    dim3 gAtt(16, 64);
    attn_mma_kernel<<<gAtt, 128, ATT_SMEM>>>();

    ff_kernel<<<(BB * SS) / 4, 256>>>(Wf, bf, out);
}

// round 15
// speedup vs baseline: 1.5700x; 1.0468x over previous
#include <cuda_runtime.h>
#include <cuda_fp16.h>
#include <math.h>
#include <stdint.h>

#define BB  4
#define SS  1024
#define DD  1024
#define HH  16
#define DHH 64
#define NFLAT 3072   // q:0-1023, k:1024-2047, v:2048-3071

// ---- persistent scratch (no allocations allowed) ----
__device__ float g_z[BB*HH*SS*DHH];     // per-head attention output

__device__ __half g_xh[BB*SS*DD];       // x as single fp16 (A operand)
__device__ __half g_whi[NFLAT*DD];      // W transposed [n][k], fp16 hi
__device__ __half g_wlo[NFLAT*DD];      // fp16 lo

// attention operands, [bh][s][e]
__device__ __half g_q[64*SS*DHH];       // Q single fp16
__device__ __half g_khi[64*SS*DHH];
__device__ __half g_klo[64*SS*DHH];
__device__ __half g_vhi[64*SS*DHH];
__device__ __half g_vlo[64*SS*DHH];

// ff path
__device__ __half g_sumh[BB*SS*DHH];    // head-sum, single fp16 [t][e]
__device__ __half g_wfhi[DD*DHH];       // Wf^T [col][e] fp16 hi
__device__ __half g_wflo[DD*DHH];       // fp16 lo

// ============================================================
// helpers
// ============================================================
__device__ __forceinline__ uint32_t smem_u32(const void* p) {
    uint32_t a;
    asm("{ .reg .u64 t; cvta.to.shared.u64 t, %1; cvt.u32.u64 %0, t; }"
        : "=r"(a) : "l"(p));
    return a;
}

#define CP16(dst, src) \
    asm volatile("cp.async.cg.shared.global [%0], [%1], 16;" \
                 :: "r"(dst), "l"(src) : "memory")
#define CP_COMMIT() asm volatile("cp.async.commit_group;" ::: "memory")
#define CP_WAIT1()  asm volatile("cp.async.wait_group 1;" ::: "memory")
#define CP_WAIT0()  asm volatile("cp.async.wait_group 0;" ::: "memory")

#define LDSM_X4(R, addr) \
    asm volatile("ldmatrix.sync.aligned.m8n8.x4.shared.b16 {%0,%1,%2,%3}, [%4];" \
                 : "=r"((R)[0]), "=r"((R)[1]), "=r"((R)[2]), "=r"((R)[3]) \
                 : "r"(addr))

#define LDSM_X4_T(R, addr) \
    asm volatile("ldmatrix.sync.aligned.m8n8.x4.trans.shared.b16 {%0,%1,%2,%3}, [%4];" \
                 : "=r"((R)[0]), "=r"((R)[1]), "=r"((R)[2]), "=r"((R)[3]) \
                 : "r"(addr))

#define MMAF16(D, A, B) \
    asm volatile("mma.sync.aligned.m16n8k16.row.col.f32.f16.f16.f32 " \
                 "{%0,%1,%2,%3}, {%4,%5,%6,%7}, {%8,%9}, {%0,%1,%2,%3};" \
                 : "+f"((D)[0]), "+f"((D)[1]), "+f"((D)[2]), "+f"((D)[3]) \
                 : "r"((A)[0]), "r"((A)[1]), "r"((A)[2]), "r"((A)[3]), \
                   "r"((B)[0]), "r"((B)[1]))

__device__ __forceinline__ uint32_t pack_h16x2(float a, float b) {
    uint32_t r;
    asm("cvt.rn.f16x2.f32 %0, %1, %2;" : "=r"(r) : "f"(b), "f"(a));
    return r;
}

// ============================================================
// Fused split kernel:
//   [0, 4096)       : x -> g_xh (single fp16)
//   [4096, 4864)    : Wq/Wk/Wv transpose + fp16 hi/lo
//   [4864, 4880)    : Wf transpose + fp16 hi/lo -> g_wfhi/g_wflo
// ============================================================
__global__ __launch_bounds__(256) void split_all_kernel(
    const float* __restrict__ x,
    const float* __restrict__ Wq, const float* __restrict__ Wk,
    const float* __restrict__ Wv, const float* __restrict__ Wf)
{
    const int tid = threadIdx.x;
    if (blockIdx.x < 4096) {
        int i4 = blockIdx.x * 256 + tid;
        float4 v = ((const float4*)x)[i4];
        __half2* ph = (__half2*)g_xh;
        ph[i4 * 2]     = __half2(__float2half_rn(v.x), __float2half_rn(v.y));
        ph[i4 * 2 + 1] = __half2(__float2half_rn(v.z), __float2half_rn(v.w));
        return;
    }
    __shared__ float ts[64][65];
    if (blockIdx.x >= 4096 + 768) {
        // Wf chunk: Wf[e][c*64+col] -> WfT[c*64+col][e]
        const int c = blockIdx.x - (4096 + 768);   // 0..15
        #pragma unroll
        for (int j = 0; j < 16; j++) {
            int lin = j * 256 + tid;
            int e = lin >> 6, col = lin & 63;
            ts[e][col] = Wf[(size_t)e * DD + c * 64 + col];
        }
        __syncthreads();
        #pragma unroll
        for (int j = 0; j < 16; j++) {
            int lin = j * 256 + tid;
            int col = lin >> 6, e = lin & 63;
            float v = ts[e][col];
            __half hi = __float2half_rn(v);
            __half lo = __float2half_rn(v - __half2float(hi));
            size_t o = (size_t)(c * 64 + col) * DHH + e;
            g_wfhi[o] = hi;
            g_wflo[o] = lo;
        }
        return;
    }
    const int bid = blockIdx.x - 4096;
    const int hf = bid >> 4;
    const int kc = bid & 15;
    const int t = hf >> 4;
    const int h = hf & 15;
    const int k0 = kc * 64;
    const float* W = (t == 0 ? Wq : (t == 1 ? Wk : Wv)) + (size_t)h * DD * DHH;

    #pragma unroll
    for (int j = 0; j < 16; j++) {
        int lin = j * 256 + tid;
        int kk = lin >> 6, e = lin & 63;
        ts[kk][e] = W[(size_t)(k0 + kk) * DHH + e];
    }
    __syncthreads();
    #pragma unroll
    for (int j = 0; j < 16; j++) {
        int lin = j * 256 + tid;
        int e = lin >> 6, kk = lin & 63;
        float v = ts[kk][e];
        __half hi = __float2half_rn(v);
        __half lo = __float2half_rn(v - __half2float(hi));
        size_t o = ((size_t)(t * 1024 + h * 64 + e)) * DD + k0 + kk;
        g_whi[o] = hi;
        g_wlo[o] = lo;
    }
}

// ============================================================
// QKV projection, fp16 2-product (unchanged from R14)
// ============================================================
#define T_A  0u
#define T_BH 16384u
#define T_BL 32768u
#define STAGE_BYTES 49152u

__device__ __forceinline__ void qkv_load_stage(uint32_t sb, int stage,
                                               int m0, int n0, int k0)
{
    const int tid = threadIdx.x;
    const char* pA  = (const char*)g_xh;
    const char* pBh = (const char*)g_whi;
    const char* pBl = (const char*)g_wlo;
    uint32_t base = sb + stage * STAGE_BYTES;
    #pragma unroll
    for (int i = 0; i < 4; i++) {
        int chunk = tid + i * 256;
        int r = chunk >> 3;
        int c = chunk & 7;
        uint32_t off = r * 128 + (((uint32_t)(c ^ (r & 7))) << 4);
        size_t ga = ((size_t)(m0 + r) * DD + k0) * 2 + c * 16;
        size_t gb = ((size_t)(n0 + r) * DD + k0) * 2 + c * 16;
        CP16(base + T_A + off, pA + ga);
        CP16(base + T_BH + off, pBh + gb);
        CP16(base + T_BL + off, pBl + gb);
    }
}

__global__ __launch_bounds__(256) void qkv_mma_kernel(
    const float* __restrict__ bq, const float* __restrict__ bk,
    const float* __restrict__ bv)
{
    extern __shared__ char dsm[];
    const uint32_t sb = smem_u32(dsm);

    const int tid = threadIdx.x;
    const int wid = tid >> 5;
    const int lane = tid & 31;
    const int warp_m = wid >> 2;
    const int warp_n = wid & 3;
    const int n0 = blockIdx.x * 128;
    const int m0 = blockIdx.y * 128;

    float acc[4][4][4];
    #pragma unroll
    for (int i = 0; i < 4; i++)
        #pragma unroll
        for (int j = 0; j < 4; j++)
            #pragma unroll
            for (int v = 0; v < 4; v++) acc[i][j][v] = 0.f;

    qkv_load_stage(sb, 0, m0, n0, 0);
    CP_COMMIT();

    for (int kb = 0; kb < 16; kb++) {
        if (kb < 15) {
            qkv_load_stage(sb, (kb + 1) & 1, m0, n0, (kb + 1) * 64);
            CP_COMMIT();
            CP_WAIT1();
        } else {
            CP_WAIT0();
        }
        __syncthreads();

        const uint32_t stg = sb + (kb & 1) * STAGE_BYTES;
        #pragma unroll
        for (int s = 0; s < 4; s++) {
            uint32_t ah[16];
            #pragma unroll
            for (int mt = 0; mt < 4; mt++) {
                int r = warp_m * 64 + mt * 16 + (lane & 15);
                int c = 2 * s + (lane >> 4);
                uint32_t off = r * 128 + (((uint32_t)(c ^ (r & 7))) << 4);
                LDSM_X4(&ah[mt * 4], stg + T_A + off);
            }
            uint32_t bh[8], bl[8];
            #pragma unroll
            for (int bt = 0; bt < 2; bt++) {
                int nr = warp_n * 32 + bt * 16 + ((lane >> 4) << 3) + (lane & 7);
                int c = 2 * s + ((lane >> 3) & 1);
                uint32_t off = nr * 128 + (((uint32_t)(c ^ (nr & 7))) << 4);
                LDSM_X4(&bh[bt * 4], stg + T_BH + off);
                LDSM_X4(&bl[bt * 4], stg + T_BL + off);
            }
            #pragma unroll
            for (int mt = 0; mt < 4; mt++)
                #pragma unroll
                for (int nt = 0; nt < 4; nt++) {
                    int bi = (nt >> 1) * 4 + (nt & 1) * 2;
                    MMAF16(acc[mt][nt], &ah[mt * 4], &bh[bi]);
                }
            #pragma unroll
            for (int mt = 0; mt < 4; mt++)
                #pragma unroll
                for (int nt = 0; nt < 4; nt++) {
                    int bi = (nt >> 1) * 4 + (nt & 1) * 2;
                    MMAF16(acc[mt][nt], &ah[mt * 4], &bl[bi]);
                }
        }
        __syncthreads();
    }

    #pragma unroll
    for (int nt = 0; nt < 4; nt++) {
        int n = n0 + warp_n * 32 + nt * 8 + (lane & 3) * 2;
        int t = n >> 10;
        int h = (n >> 6) & 15;
        int e = n & 63;
        const float* bias = (t == 0 ? bq : (t == 1 ? bk : bv));
        float b0v = bias[h * 64 + e];
        float b1v = bias[h * 64 + e + 1];
        #pragma unroll
        for (int mt = 0; mt < 4; mt++) {
            #pragma unroll
            for (int half = 0; half < 2; half++) {
                int row = m0 + warp_m * 64 + mt * 16 + (lane >> 2) + half * 8;
                int b = row >> 10;
                int s = row & 1023;
                int bh = b * HH + h;
                float v0 = acc[mt][nt][half * 2]     + b0v;
                float v1 = acc[mt][nt][half * 2 + 1] + b1v;
                __half h0 = __float2half_rn(v0);
                __half h1 = __float2half_rn(v1);
                size_t o = ((size_t)(bh << 10) + s) * 64 + e;
                if (t == 0) {
                    *(__half2*)&g_q[o] = __half2(h0, h1);
                } else {
                    __half l0 = __float2half_rn(v0 - __half2float(h0));
                    __half l1 = __float2half_rn(v1 - __half2float(h1));
                    __half* dhi = (t == 1 ? g_khi : g_vhi);
                    __half* dlo = (t == 1 ? g_klo : g_vlo);
                    *(__half2*)&dhi[o] = __half2(h0, h1);
                    *(__half2*)&dlo[o] = __half2(l0, l1);
                }
            }
        }
    }
}

// ============================================================
// Flash attention, fp16 2-product (unchanged from R14)
// ============================================================
#define AST    0u
#define AST_SZ 32768u
#define AQ     65536u

__device__ __forceinline__ void attn_load_kv(uint32_t stg, int bh, int k0)
{
    const int tid = threadIdx.x;
    const char* kh = (const char*)g_khi;
    const char* kl = (const char*)g_klo;
    const char* vh = (const char*)g_vhi;
    const char* vl = (const char*)g_vlo;
    #pragma unroll
    for (int i = 0; i < 4; i++) {
        int ch = i * 128 + tid;
        int r = ch >> 3;
        int c = ch & 7;
        uint32_t off = r * 128 + (((uint32_t)(c ^ (r & 7))) << 4);
        size_t src = ((size_t)((bh << 10) + k0 + r)) * 128 + c * 16;
        CP16(stg + 0 + off, kh + src);
        CP16(stg + 8192 + off, kl + src);
        CP16(stg + 16384 + off, vh + src);
        CP16(stg + 24576 + off, vl + src);
    }
}

__global__ __launch_bounds__(128) void attn_mma_kernel()
{
    extern __shared__ char dsm[];
    const uint32_t sb = smem_u32(dsm);

    const int tid = threadIdx.x;
    const int wid = tid >> 5;
    const int lane = tid & 31;
    const int qt = 15 - blockIdx.x;
    const int bh = blockIdx.y;
    const int q0 = qt * 64;
    const int n_kt = qt + 1;

    {
        const char* qp = (const char*)g_q;
        #pragma unroll
        for (int i = 0; i < 4; i++) {
            int ch = i * 128 + tid;
            int r = ch >> 3;
            int c = ch & 7;
            uint32_t off = r * 128 + (((uint32_t)(c ^ (r & 7))) << 4);
            size_t src = ((size_t)((bh << 10) + q0 + r)) * 128 + c * 16;
            CP16(sb + AQ + off, qp + src);
        }
        attn_load_kv(sb + AST, bh, 0);
        CP_COMMIT();
    }

    float o[8][4];
    #pragma unroll
    for (int i = 0; i < 8; i++)
        #pragma unroll
        for (int j = 0; j < 4; j++) o[i][j] = 0.f;
    float m[2] = {-1e30f, -1e30f};
    float l[2] = {0.f, 0.f};
    uint32_t qf[16];
    const int wr0 = q0 + wid * 16;

    for (int kt = 0; kt < n_kt; kt++) {
        if (kt + 1 < n_kt) {
            attn_load_kv(sb + AST + ((kt + 1) & 1) * AST_SZ, bh, (kt + 1) * 64);
            CP_COMMIT();
            CP_WAIT1();
        } else {
            CP_WAIT0();
        }
        __syncthreads();

        if (kt == 0) {
            #pragma unroll
            for (int ks = 0; ks < 4; ks++) {
                int r = wid * 16 + (lane & 15);
                int c = 2 * ks + (lane >> 4);
                uint32_t off = r * 128 + (((uint32_t)(c ^ (r & 7))) << 4);
                LDSM_X4(&qf[ks * 4], sb + AQ + off);
            }
        }

        const int k0 = kt * 64;
        const uint32_t stg = sb + AST + (kt & 1) * AST_SZ;

        float sc[8][4];
        #pragma unroll
        for (int i = 0; i < 8; i++)
            #pragma unroll
            for (int j = 0; j < 4; j++) sc[i][j] = 0.f;
        #pragma unroll
        for (int ks = 0; ks < 4; ks++) {
            uint32_t kfh[16], kfl[16];
            #pragma unroll
            for (int nt2 = 0; nt2 < 4; nt2++) {
                int nr = nt2 * 16 + ((lane >> 4) << 3) + (lane & 7);
                int c = 2 * ks + ((lane >> 3) & 1);
                uint32_t off = nr * 128 + (((uint32_t)(c ^ (nr & 7))) << 4);
                LDSM_X4(&kfh[nt2 * 4], stg + 0 + off);
                LDSM_X4(&kfl[nt2 * 4], stg + 8192 + off);
            }
            #pragma unroll
            for (int nt = 0; nt < 8; nt++) {
                int bi = (nt >> 1) * 4 + (nt & 1) * 2;
                MMAF16(sc[nt], &qf[ks * 4], &kfh[bi]);
            }
            #pragma unroll
            for (int nt = 0; nt < 8; nt++) {
                int bi = (nt >> 1) * 4 + (nt & 1) * 2;
                MMAF16(sc[nt], &qf[ks * 4], &kfl[bi]);
            }
        }
        const bool need_mask = (k0 + 63 > wr0);
        uint32_t ph[16];
        float alpha[2];
        #pragma unroll
        for (int rs = 0; rs < 2; rs++) {
            int grow = wr0 + (lane >> 2) + rs * 8;
            float mx = -1e30f;
            #pragma unroll
            for (int nt = 0; nt < 8; nt++) {
                float v0 = sc[nt][rs * 2] * 0.125f;
                float v1 = sc[nt][rs * 2 + 1] * 0.125f;
                if (need_mask) {
                    int gc = k0 + nt * 8 + 2 * (lane & 3);
                    if (gc > grow) v0 = -1e30f;
                    if (gc + 1 > grow) v1 = -1e30f;
                }
                sc[nt][rs * 2] = v0;
                sc[nt][rs * 2 + 1] = v1;
                mx = fmaxf(mx, fmaxf(v0, v1));
            }
            mx = fmaxf(mx, __shfl_xor_sync(0xffffffffu, mx, 1));
            mx = fmaxf(mx, __shfl_xor_sync(0xffffffffu, mx, 2));
            float mn = fmaxf(m[rs], mx);
            alpha[rs] = __expf(m[rs] - mn);
            m[rs] = mn;
            float rsum = 0.f;
            #pragma unroll
            for (int nt = 0; nt < 8; nt++) {
                float p0 = __expf(sc[nt][rs * 2] - mn);
                float p1 = __expf(sc[nt][rs * 2 + 1] - mn);
                rsum += p0 + p1;
                int idx = (nt >> 1) * 4 + (nt & 1) * 2 + rs;
                ph[idx] = pack_h16x2(p0, p1);
            }
            rsum += __shfl_xor_sync(0xffffffffu, rsum, 1);
            rsum += __shfl_xor_sync(0xffffffffu, rsum, 2);
            l[rs] = l[rs] * alpha[rs] + rsum;
            #pragma unroll
            for (int ne = 0; ne < 8; ne++) {
                o[ne][rs * 2] *= alpha[rs];
                o[ne][rs * 2 + 1] *= alpha[rs];
            }
        }
        #pragma unroll
        for (int kp = 0; kp < 4; kp++) {
            uint32_t vfh[16], vfl[16];
            #pragma unroll
            for (int ne2 = 0; ne2 < 4; ne2++) {
                int r = kp * 16 + (lane & 15);
                int c = ne2 * 2 + (lane >> 4);
                uint32_t off = r * 128 + (((uint32_t)(c ^ (r & 7))) << 4);
                LDSM_X4_T(&vfh[ne2 * 4], stg + 16384 + off);
                LDSM_X4_T(&vfl[ne2 * 4], stg + 24576 + off);
            }
            #pragma unroll
            for (int ne = 0; ne < 8; ne++) {
                int bi = (ne >> 1) * 4 + (ne & 1) * 2;
                MMAF16(o[ne], &ph[kp * 4], &vfh[bi]);
            }
            #pragma unroll
            for (int ne = 0; ne < 8; ne++) {
                int bi = (ne >> 1) * 4 + (ne & 1) * 2;
                MMAF16(o[ne], &ph[kp * 4], &vfl[bi]);
            }
        }
        __syncthreads();
    }

    #pragma unroll
    for (int rs = 0; rs < 2; rs++) {
        float inv = 1.f / l[rs];
        int row = wr0 + (lane >> 2) + rs * 8;
        #pragma unroll
        for (int ne = 0; ne < 8; ne++) {
            int e = ne * 8 + 2 * (lane & 3);
            float2 r2;
            r2.x = o[ne][rs * 2] * inv;
            r2.y = o[ne][rs * 2 + 1] * inv;
            *(float2*)&g_z[((size_t)(bh << 10) + row) * 64 + e] = r2;
        }
    }
}

// ============================================================
// Head-sum -> single fp16 g_sumh
// ============================================================
__global__ __launch_bounds__(256) void headsum_kernel()
{
    int idx2 = blockIdx.x * 256 + threadIdx.x;   // over 131072 half2
    int e2 = idx2 & 31;                          // half2 index within row
    int s = (idx2 >> 5) & 1023;
    int b = idx2 >> 15;
    const float* zp = g_z + ((size_t)(b * HH) * SS + s) * DHH + e2 * 2;
    float a0 = 0.f, a1 = 0.f;
    #pragma unroll
    for (int h = 0; h < HH; h++) {
        a0 += zp[(size_t)h * SS * DHH];
        a1 += zp[(size_t)h * SS * DHH + 1];
    }
    ((__half2*)g_sumh)[idx2] = __half2(__float2half_rn(a0), __float2half_rn(a1));
}

// ============================================================
// FF via fp16 tensor: out = gelu(sum @ Wf + bf).
// CTA tile 128 tok x 128 col, K=64 single shot. smem 48KB.
// A = g_sumh (single), B = WfT hi/lo (2-product).
// ============================================================
__device__ __forceinline__ float gelu_exact(float v)
{
    return 0.5f * v * (1.0f + erff(v * 0.70710678118654752f));
}

#define F_A  0u
#define F_BH 16384u
#define F_BL 32768u

__global__ __launch_bounds__(256) void ff_mma_kernel(
    const float* __restrict__ bf, float* __restrict__ out)
{
    extern __shared__ char dsm[];
    const uint32_t sb = smem_u32(dsm);

    const int tid = threadIdx.x;
    const int wid = tid >> 5;
    const int lane = tid & 31;
    const int warp_m = wid >> 2;
    const int warp_n = wid & 3;
    const int c0 = blockIdx.x * 128;
    const int t0 = blockIdx.y * 128;

    // load A (tokens x 64e) and B (cols x 64e) hi/lo, 64B rows doubled to 128B?
    // rows are 64 e * 2B = 128B: exactly 8 chunks of 16B.
    {
        const char* pA  = (const char*)g_sumh;
        const char* pBh = (const char*)g_wfhi;
        const char* pBl = (const char*)g_wflo;
        #pragma unroll
        for (int i = 0; i < 4; i++) {
            int chunk = tid + i * 256;            // 0..1023
            int r = chunk >> 3;
            int c = chunk & 7;
            uint32_t off = r * 128 + (((uint32_t)(c ^ (r & 7))) << 4);
            size_t ga = ((size_t)(t0 + r) * DHH) * 2 + c * 16;
            size_t gb = ((size_t)(c0 + r) * DHH) * 2 + c * 16;
            CP16(sb + F_A + off, pA + ga);
            CP16(sb + F_BH + off, pBh + gb);
            CP16(sb + F_BL + off, pBl + gb);
        }
        CP_COMMIT();
        CP_WAIT0();
        __syncthreads();
    }

    float acc[4][4][4];
    #pragma unroll
    for (int i = 0; i < 4; i++)
        #pragma unroll
        for (int j = 0; j < 4; j++)
            #pragma unroll
            for (int v = 0; v < 4; v++) acc[i][j][v] = 0.f;

    #pragma unroll
    for (int ks = 0; ks < 4; ks++) {
        uint32_t ah[16];
        #pragma unroll
        for (int mt = 0; mt < 4; mt++) {
            int r = warp_m * 64 + mt * 16 + (lane & 15);
            int c = 2 * ks + (lane >> 4);
            uint32_t off = r * 128 + (((uint32_t)(c ^ (r & 7))) << 4);
            LDSM_X4(&ah[mt * 4], sb + F_A + off);
        }
        uint32_t bh[8], bl[8];
        #pragma unroll
        for (int bt = 0; bt < 2; bt++) {
            int nr = warp_n * 32 + bt * 16 + ((lane >> 4) << 3) + (lane & 7);
            int c = 2 * ks + ((lane >> 3) & 1);
            uint32_t off = nr * 128 + (((uint32_t)(c ^ (nr & 7))) << 4);
            LDSM_X4(&bh[bt * 4], sb + F_BH + off);
            LDSM_X4(&bl[bt * 4], sb + F_BL + off);
        }
        #pragma unroll
        for (int mt = 0; mt < 4; mt++)
            #pragma unroll
            for (int nt = 0; nt < 4; nt++) {
                int bi = (nt >> 1) * 4 + (nt & 1) * 2;
                MMAF16(acc[mt][nt], &ah[mt * 4], &bh[bi]);
            }
        #pragma unroll
        for (int mt = 0; mt < 4; mt++)
            #pragma unroll
            for (int nt = 0; nt < 4; nt++) {
                int bi = (nt >> 1) * 4 + (nt & 1) * 2;
                MMAF16(acc[mt][nt], &ah[mt * 4], &bl[bi]);
            }
    }

    // epilogue: bias + exact gelu + store
    #pragma unroll
    for (int nt = 0; nt < 4; nt++) {
        int col = c0 + warp_n * 32 + nt * 8 + (lane & 3) * 2;
        float b0v = bf[col];
        float b1v = bf[col + 1];
        #pragma unroll
        for (int mt = 0; mt < 4; mt++) {
            #pragma unroll
            for (int half = 0; half < 2; half++) {
                int tok = t0 + warp_m * 64 + mt * 16 + (lane >> 2) + half * 8;
                float2 r2;
                r2.x = gelu_exact(acc[mt][nt][half * 2]     + b0v);
                r2.y = gelu_exact(acc[mt][nt][half * 2 + 1] + b1v);
                *(float2*)&out[(size_t)tok * DD + col] = r2;
            }
        }
    }
}

// ============================================================
extern "C" void kernel_launch(void* const* d_in, const int* in_sizes, int n_in,
                              void* d_out, int out_size)
{
    const float* x  = (const float*)d_in[0];
    const float* Wq = (const float*)d_in[1];
    const float* bq = (const float*)d_in[2];
    const float* Wk = (const float*)d_in[3];
    const float* bk = (const float*)d_in[4];
    const float* Wv = (const float*)d_in[5];
    const float* bv = (const float*)d_in[6];
    const float* Wf = (const float*)d_in[7];
    const float* bf = (const float*)d_in[8];
    float* out = (float*)d_out;

    static const int QKV_SMEM = 98304;    // 2 stages x 48KB
    static const int ATT_SMEM = 73728;    // 2 stages x 32KB + Q 8KB
    static const int FF_SMEM  = 49152;    // A + BH + BL
    cudaFuncSetAttribute(qkv_mma_kernel,
                         cudaFuncAttributeMaxDynamicSharedMemorySize, QKV_SMEM);
    cudaFuncSetAttribute(attn_mma_kernel,
                         cudaFuncAttributeMaxDynamicSharedMemorySize, ATT_SMEM);
    cudaFuncSetAttribute(ff_mma_kernel,
                         cudaFuncAttributeMaxDynamicSharedMemorySize, FF_SMEM);

    split_all_kernel<<<4096 + 768 + 16, 256>>>(x, Wq, Wk, Wv, Wf);

    dim3 gMMA(NFLAT / 128, (BB * SS) / 128);
    qkv_mma_kernel<<<gMMA, 256, QKV_SMEM>>>(bq, bk, bv);

    dim3 gAtt(16, 64);
    attn_mma_kernel<<<gAtt, 128, ATT_SMEM>>>();

    headsum_kernel<<<(BB * SS * DHH / 2) / 256, 256>>>();

    dim3 gFF(DD / 128, (BB * SS) / 128);
    ff_mma_kernel<<<gFF, 256, FF_SMEM>>>(bf, out);
}

// round 16
// speedup vs baseline: 1.5992x; 1.0186x over previous
#include <cuda_runtime.h>
#include <cuda_fp16.h>
#include <math.h>
#include <stdint.h>

#define BB  4
#define SS  1024
#define DD  1024
#define HH  16
#define DHH 64
#define NFLAT 3072   // q:0-1023, k:1024-2047, v:2048-3071

// ---- persistent scratch (no allocations allowed) ----
__device__ __half g_zh[BB*HH*SS*DHH];   // per-head attention output (fp16)

__device__ __half g_xh[BB*SS*DD];       // x as single fp16 (A operand)
__device__ __half g_whi[NFLAT*DD];      // W transposed [n][k], fp16 hi
__device__ __half g_wlo[NFLAT*DD];      // fp16 lo

// attention operands, [bh][s][e]
__device__ __half g_q[64*SS*DHH];       // Q single fp16
__device__ __half g_khi[64*SS*DHH];
__device__ __half g_klo[64*SS*DHH];
__device__ __half g_vhi[64*SS*DHH];
__device__ __half g_vlo[64*SS*DHH];

// ff path
__device__ __half g_sumh[BB*SS*DHH];    // head-sum, single fp16 [t][e]
__device__ __half g_wfhi[DD*DHH];       // Wf^T [col][e] fp16 hi
__device__ __half g_wflo[DD*DHH];       // fp16 lo

// ============================================================
// helpers
// ============================================================
__device__ __forceinline__ uint32_t smem_u32(const void* p) {
    uint32_t a;
    asm("{ .reg .u64 t; cvta.to.shared.u64 t, %1; cvt.u32.u64 %0, t; }"
        : "=r"(a) : "l"(p));
    return a;
}

#define CP16(dst, src) \
    asm volatile("cp.async.cg.shared.global [%0], [%1], 16;" \
                 :: "r"(dst), "l"(src) : "memory")
#define CP_COMMIT() asm volatile("cp.async.commit_group;" ::: "memory")
#define CP_WAIT1()  asm volatile("cp.async.wait_group 1;" ::: "memory")
#define CP_WAIT0()  asm volatile("cp.async.wait_group 0;" ::: "memory")

#define LDSM_X4(R, addr) \
    asm volatile("ldmatrix.sync.aligned.m8n8.x4.shared.b16 {%0,%1,%2,%3}, [%4];" \
                 : "=r"((R)[0]), "=r"((R)[1]), "=r"((R)[2]), "=r"((R)[3]) \
                 : "r"(addr))

#define LDSM_X4_T(R, addr) \
    asm volatile("ldmatrix.sync.aligned.m8n8.x4.trans.shared.b16 {%0,%1,%2,%3}, [%4];" \
                 : "=r"((R)[0]), "=r"((R)[1]), "=r"((R)[2]), "=r"((R)[3]) \
                 : "r"(addr))

#define MMAF16(D, A, B) \
    asm volatile("mma.sync.aligned.m16n8k16.row.col.f32.f16.f16.f32 " \
                 "{%0,%1,%2,%3}, {%4,%5,%6,%7}, {%8,%9}, {%0,%1,%2,%3};" \
                 : "+f"((D)[0]), "+f"((D)[1]), "+f"((D)[2]), "+f"((D)[3]) \
                 : "r"((A)[0]), "r"((A)[1]), "r"((A)[2]), "r"((A)[3]), \
                   "r"((B)[0]), "r"((B)[1]))

__device__ __forceinline__ uint32_t pack_h16x2(float a, float b) {
    uint32_t r;
    asm("cvt.rn.f16x2.f32 %0, %1, %2;" : "=r"(r) : "f"(b), "f"(a));
    return r;
}

// ============================================================
// Fused split kernel:
//   [0, 4096)       : x -> g_xh (single fp16)
//   [4096, 4864)    : Wq/Wk/Wv transpose + fp16 hi/lo
//   [4864, 4880)    : Wf transpose + fp16 hi/lo
// ============================================================
__global__ __launch_bounds__(256) void split_all_kernel(
    const float* __restrict__ x,
    const float* __restrict__ Wq, const float* __restrict__ Wk,
    const float* __restrict__ Wv, const float* __restrict__ Wf)
{
    const int tid = threadIdx.x;
    if (blockIdx.x < 4096) {
        int i4 = blockIdx.x * 256 + tid;
        float4 v = ((const float4*)x)[i4];
        __half2* ph = (__half2*)g_xh;
        ph[i4 * 2]     = __half2(__float2half_rn(v.x), __float2half_rn(v.y));
        ph[i4 * 2 + 1] = __half2(__float2half_rn(v.z), __float2half_rn(v.w));
        return;
    }
    __shared__ float ts[64][65];
    if (blockIdx.x >= 4096 + 768) {
        const int c = blockIdx.x - (4096 + 768);   // 0..15
        #pragma unroll
        for (int j = 0; j < 16; j++) {
            int lin = j * 256 + tid;
            int e = lin >> 6, col = lin & 63;
            ts[e][col] = Wf[(size_t)e * DD + c * 64 + col];
        }
        __syncthreads();
        #pragma unroll
        for (int j = 0; j < 16; j++) {
            int lin = j * 256 + tid;
            int col = lin >> 6, e = lin & 63;
            float v = ts[e][col];
            __half hi = __float2half_rn(v);
            __half lo = __float2half_rn(v - __half2float(hi));
            size_t o = (size_t)(c * 64 + col) * DHH + e;
            g_wfhi[o] = hi;
            g_wflo[o] = lo;
        }
        return;
    }
    const int bid = blockIdx.x - 4096;
    const int hf = bid >> 4;
    const int kc = bid & 15;
    const int t = hf >> 4;
    const int h = hf & 15;
    const int k0 = kc * 64;
    const float* W = (t == 0 ? Wq : (t == 1 ? Wk : Wv)) + (size_t)h * DD * DHH;

    #pragma unroll
    for (int j = 0; j < 16; j++) {
        int lin = j * 256 + tid;
        int kk = lin >> 6, e = lin & 63;
        ts[kk][e] = W[(size_t)(k0 + kk) * DHH + e];
    }
    __syncthreads();
    #pragma unroll
    for (int j = 0; j < 16; j++) {
        int lin = j * 256 + tid;
        int e = lin >> 6, kk = lin & 63;
        float v = ts[kk][e];
        __half hi = __float2half_rn(v);
        __half lo = __float2half_rn(v - __half2float(hi));
        size_t o = ((size_t)(t * 1024 + h * 64 + e)) * DD + k0 + kk;
        g_whi[o] = hi;
        g_wlo[o] = lo;
    }
}

// ============================================================
// QKV projection, fp16 2-product; now 2 CTAs/SM (96 fragment regs fits 128 cap)
// ============================================================
#define T_A  0u
#define T_BH 16384u
#define T_BL 32768u
#define STAGE_BYTES 49152u

__device__ __forceinline__ void qkv_load_stage(uint32_t sb, int stage,
                                               int m0, int n0, int k0)
{
    const int tid = threadIdx.x;
    const char* pA  = (const char*)g_xh;
    const char* pBh = (const char*)g_whi;
    const char* pBl = (const char*)g_wlo;
    uint32_t base = sb + stage * STAGE_BYTES;
    #pragma unroll
    for (int i = 0; i < 4; i++) {
        int chunk = tid + i * 256;
        int r = chunk >> 3;
        int c = chunk & 7;
        uint32_t off = r * 128 + (((uint32_t)(c ^ (r & 7))) << 4);
        size_t ga = ((size_t)(m0 + r) * DD + k0) * 2 + c * 16;
        size_t gb = ((size_t)(n0 + r) * DD + k0) * 2 + c * 16;
        CP16(base + T_A + off, pA + ga);
        CP16(base + T_BH + off, pBh + gb);
        CP16(base + T_BL + off, pBl + gb);
    }
}

__global__ __launch_bounds__(256, 2) void qkv_mma_kernel(
    const float* __restrict__ bq, const float* __restrict__ bk,
    const float* __restrict__ bv)
{
    extern __shared__ char dsm[];
    const uint32_t sb = smem_u32(dsm);

    const int tid = threadIdx.x;
    const int wid = tid >> 5;
    const int lane = tid & 31;
    const int warp_m = wid >> 2;
    const int warp_n = wid & 3;
    const int n0 = blockIdx.x * 128;
    const int m0 = blockIdx.y * 128;

    float acc[4][4][4];
    #pragma unroll
    for (int i = 0; i < 4; i++)
        #pragma unroll
        for (int j = 0; j < 4; j++)
            #pragma unroll
            for (int v = 0; v < 4; v++) acc[i][j][v] = 0.f;

    qkv_load_stage(sb, 0, m0, n0, 0);
    CP_COMMIT();

    for (int kb = 0; kb < 16; kb++) {
        if (kb < 15) {
            qkv_load_stage(sb, (kb + 1) & 1, m0, n0, (kb + 1) * 64);
            CP_COMMIT();
            CP_WAIT1();
        } else {
            CP_WAIT0();
        }
        __syncthreads();

        const uint32_t stg = sb + (kb & 1) * STAGE_BYTES;
        #pragma unroll
        for (int s = 0; s < 4; s++) {
            uint32_t ah[16];
            #pragma unroll
            for (int mt = 0; mt < 4; mt++) {
                int r = warp_m * 64 + mt * 16 + (lane & 15);
                int c = 2 * s + (lane >> 4);
                uint32_t off = r * 128 + (((uint32_t)(c ^ (r & 7))) << 4);
                LDSM_X4(&ah[mt * 4], stg + T_A + off);
            }
            uint32_t bh[8], bl[8];
            #pragma unroll
            for (int bt = 0; bt < 2; bt++) {
                int nr = warp_n * 32 + bt * 16 + ((lane >> 4) << 3) + (lane & 7);
                int c = 2 * s + ((lane >> 3) & 1);
                uint32_t off = nr * 128 + (((uint32_t)(c ^ (nr & 7))) << 4);
                LDSM_X4(&bh[bt * 4], stg + T_BH + off);
                LDSM_X4(&bl[bt * 4], stg + T_BL + off);
            }
            #pragma unroll
            for (int mt = 0; mt < 4; mt++)
                #pragma unroll
                for (int nt = 0; nt < 4; nt++) {
                    int bi = (nt >> 1) * 4 + (nt & 1) * 2;
                    MMAF16(acc[mt][nt], &ah[mt * 4], &bh[bi]);
                }
            #pragma unroll
            for (int mt = 0; mt < 4; mt++)
                #pragma unroll
                for (int nt = 0; nt < 4; nt++) {
                    int bi = (nt >> 1) * 4 + (nt & 1) * 2;
                    MMAF16(acc[mt][nt], &ah[mt * 4], &bl[bi]);
                }
        }
        __syncthreads();
    }

    #pragma unroll
    for (int nt = 0; nt < 4; nt++) {
        int n = n0 + warp_n * 32 + nt * 8 + (lane & 3) * 2;
        int t = n >> 10;
        int h = (n >> 6) & 15;
        int e = n & 63;
        const float* bias = (t == 0 ? bq : (t == 1 ? bk : bv));
        float b0v = bias[h * 64 + e];
        float b1v = bias[h * 64 + e + 1];
        #pragma unroll
        for (int mt = 0; mt < 4; mt++) {
            #pragma unroll
            for (int half = 0; half < 2; half++) {
                int row = m0 + warp_m * 64 + mt * 16 + (lane >> 2) + half * 8;
                int b = row >> 10;
                int s = row & 1023;
                int bh = b * HH + h;
                float v0 = acc[mt][nt][half * 2]     + b0v;
                float v1 = acc[mt][nt][half * 2 + 1] + b1v;
                __half h0 = __float2half_rn(v0);
                __half h1 = __float2half_rn(v1);
                size_t o = ((size_t)(bh << 10) + s) * 64 + e;
                if (t == 0) {
                    *(__half2*)&g_q[o] = __half2(h0, h1);
                } else {
                    __half l0 = __float2half_rn(v0 - __half2float(h0));
                    __half l1 = __float2half_rn(v1 - __half2float(h1));
                    __half* dhi = (t == 1 ? g_khi : g_vhi);
                    __half* dlo = (t == 1 ? g_klo : g_vlo);
                    *(__half2*)&dhi[o] = __half2(h0, h1);
                    *(__half2*)&dlo[o] = __half2(l0, l1);
                }
            }
        }
    }
}

// ============================================================
// Flash attention, fp16 2-product; z written as fp16
// ============================================================
#define AST    0u
#define AST_SZ 32768u
#define AQ     65536u

__device__ __forceinline__ void attn_load_kv(uint32_t stg, int bh, int k0)
{
    const int tid = threadIdx.x;
    const char* kh = (const char*)g_khi;
    const char* kl = (const char*)g_klo;
    const char* vh = (const char*)g_vhi;
    const char* vl = (const char*)g_vlo;
    #pragma unroll
    for (int i = 0; i < 4; i++) {
        int ch = i * 128 + tid;
        int r = ch >> 3;
        int c = ch & 7;
        uint32_t off = r * 128 + (((uint32_t)(c ^ (r & 7))) << 4);
        size_t src = ((size_t)((bh << 10) + k0 + r)) * 128 + c * 16;
        CP16(stg + 0 + off, kh + src);
        CP16(stg + 8192 + off, kl + src);
        CP16(stg + 16384 + off, vh + src);
        CP16(stg + 24576 + off, vl + src);
    }
}

__global__ __launch_bounds__(128) void attn_mma_kernel()
{
    extern __shared__ char dsm[];
    const uint32_t sb = smem_u32(dsm);

    const int tid = threadIdx.x;
    const int wid = tid >> 5;
    const int lane = tid & 31;
    const int qt = 15 - blockIdx.x;
    const int bh = blockIdx.y;
    const int q0 = qt * 64;
    const int n_kt = qt + 1;

    {
        const char* qp = (const char*)g_q;
        #pragma unroll
        for (int i = 0; i < 4; i++) {
            int ch = i * 128 + tid;
            int r = ch >> 3;
            int c = ch & 7;
            uint32_t off = r * 128 + (((uint32_t)(c ^ (r & 7))) << 4);
            size_t src = ((size_t)((bh << 10) + q0 + r)) * 128 + c * 16;
            CP16(sb + AQ + off, qp + src);
        }
        attn_load_kv(sb + AST, bh, 0);
        CP_COMMIT();
    }

    float o[8][4];
    #pragma unroll
    for (int i = 0; i < 8; i++)
        #pragma unroll
        for (int j = 0; j < 4; j++) o[i][j] = 0.f;
    float m[2] = {-1e30f, -1e30f};
    float l[2] = {0.f, 0.f};
    uint32_t qf[16];
    const int wr0 = q0 + wid * 16;

    for (int kt = 0; kt < n_kt; kt++) {
        if (kt + 1 < n_kt) {
            attn_load_kv(sb + AST + ((kt + 1) & 1) * AST_SZ, bh, (kt + 1) * 64);
            CP_COMMIT();
            CP_WAIT1();
        } else {
            CP_WAIT0();
        }
        __syncthreads();

        if (kt == 0) {
            #pragma unroll
            for (int ks = 0; ks < 4; ks++) {
                int r = wid * 16 + (lane & 15);
                int c = 2 * ks + (lane >> 4);
                uint32_t off = r * 128 + (((uint32_t)(c ^ (r & 7))) << 4);
                LDSM_X4(&qf[ks * 4], sb + AQ + off);
            }
        }

        const int k0 = kt * 64;
        const uint32_t stg = sb + AST + (kt & 1) * AST_SZ;

        float sc[8][4];
        #pragma unroll
        for (int i = 0; i < 8; i++)
            #pragma unroll
            for (int j = 0; j < 4; j++) sc[i][j] = 0.f;
        #pragma unroll
        for (int ks = 0; ks < 4; ks++) {
            uint32_t kfh[16], kfl[16];
            #pragma unroll
            for (int nt2 = 0; nt2 < 4; nt2++) {
                int nr = nt2 * 16 + ((lane >> 4) << 3) + (lane & 7);
                int c = 2 * ks + ((lane >> 3) & 1);
                uint32_t off = nr * 128 + (((uint32_t)(c ^ (nr & 7))) << 4);
                LDSM_X4(&kfh[nt2 * 4], stg + 0 + off);
                LDSM_X4(&kfl[nt2 * 4], stg + 8192 + off);
            }
            #pragma unroll
            for (int nt = 0; nt < 8; nt++) {
                int bi = (nt >> 1) * 4 + (nt & 1) * 2;
                MMAF16(sc[nt], &qf[ks * 4], &kfh[bi]);
            }
            #pragma unroll
            for (int nt = 0; nt < 8; nt++) {
                int bi = (nt >> 1) * 4 + (nt & 1) * 2;
                MMAF16(sc[nt], &qf[ks * 4], &kfl[bi]);
            }
        }
        const bool need_mask = (k0 + 63 > wr0);
        uint32_t ph[16];
        float alpha[2];
        #pragma unroll
        for (int rs = 0; rs < 2; rs++) {
            int grow = wr0 + (lane >> 2) + rs * 8;
            float mx = -1e30f;
            #pragma unroll
            for (int nt = 0; nt < 8; nt++) {
                float v0 = sc[nt][rs * 2] * 0.125f;
                float v1 = sc[nt][rs * 2 + 1] * 0.125f;
                if (need_mask) {
                    int gc = k0 + nt * 8 + 2 * (lane & 3);
                    if (gc > grow) v0 = -1e30f;
                    if (gc + 1 > grow) v1 = -1e30f;
                }
                sc[nt][rs * 2] = v0;
                sc[nt][rs * 2 + 1] = v1;
                mx = fmaxf(mx, fmaxf(v0, v1));
            }
            mx = fmaxf(mx, __shfl_xor_sync(0xffffffffu, mx, 1));
            mx = fmaxf(mx, __shfl_xor_sync(0xffffffffu, mx, 2));
            float mn = fmaxf(m[rs], mx);
            alpha[rs] = __expf(m[rs] - mn);
            m[rs] = mn;
            float rsum = 0.f;
            #pragma unroll
            for (int nt = 0; nt < 8; nt++) {
                float p0 = __expf(sc[nt][rs * 2] - mn);
                float p1 = __expf(sc[nt][rs * 2 + 1] - mn);
                rsum += p0 + p1;
                int idx = (nt >> 1) * 4 + (nt & 1) * 2 + rs;
                ph[idx] = pack_h16x2(p0, p1);
            }
            rsum += __shfl_xor_sync(0xffffffffu, rsum, 1);
            rsum += __shfl_xor_sync(0xffffffffu, rsum, 2);
            l[rs] = l[rs] * alpha[rs] + rsum;
            #pragma unroll
            for (int ne = 0; ne < 8; ne++) {
                o[ne][rs * 2] *= alpha[rs];
                o[ne][rs * 2 + 1] *= alpha[rs];
            }
        }
        #pragma unroll
        for (int kp = 0; kp < 4; kp++) {
            uint32_t vfh[16], vfl[16];
            #pragma unroll
            for (int ne2 = 0; ne2 < 4; ne2++) {
                int r = kp * 16 + (lane & 15);
                int c = ne2 * 2 + (lane >> 4);
                uint32_t off = r * 128 + (((uint32_t)(c ^ (r & 7))) << 4);
                LDSM_X4_T(&vfh[ne2 * 4], stg + 16384 + off);
                LDSM_X4_T(&vfl[ne2 * 4], stg + 24576 + off);
            }
            #pragma unroll
            for (int ne = 0; ne < 8; ne++) {
                int bi = (ne >> 1) * 4 + (ne & 1) * 2;
                MMAF16(o[ne], &ph[kp * 4], &vfh[bi]);
            }
            #pragma unroll
            for (int ne = 0; ne < 8; ne++) {
                int bi = (ne >> 1) * 4 + (ne & 1) * 2;
                MMAF16(o[ne], &ph[kp * 4], &vfl[bi]);
            }
        }
        __syncthreads();
    }

    // ---- normalize + write fp16 ----
    #pragma unroll
    for (int rs = 0; rs < 2; rs++) {
        float inv = 1.f / l[rs];
        int row = wr0 + (lane >> 2) + rs * 8;
        #pragma unroll
        for (int ne = 0; ne < 8; ne++) {
            int e = ne * 8 + 2 * (lane & 3);
            uint32_t pk = pack_h16x2(o[ne][rs * 2] * inv, o[ne][rs * 2 + 1] * inv);
            *(uint32_t*)&g_zh[((size_t)(bh << 10) + row) * 64 + e] = pk;
        }
    }
}

// ============================================================
// Head-sum (fp16 in, fp32 accum) -> single fp16 g_sumh
// ============================================================
__global__ __launch_bounds__(256) void headsum_kernel()
{
    int idx2 = blockIdx.x * 256 + threadIdx.x;   // over 131072 half2
    int e2 = idx2 & 31;
    int s = (idx2 >> 5) & 1023;
    int b = idx2 >> 15;
    const __half2* zp = (const __half2*)(g_zh + ((size_t)(b * HH) * SS + s) * DHH) + e2;
    float a0 = 0.f, a1 = 0.f;
    #pragma unroll
    for (int h = 0; h < HH; h++) {
        __half2 v = zp[(size_t)h * SS * DHH / 2];
        a0 += __low2float(v);
        a1 += __high2float(v);
    }
    ((__half2*)g_sumh)[idx2] = __half2(__float2half_rn(a0), __float2half_rn(a1));
}

// ============================================================
// FF via fp16 tensor (unchanged from R15)
// ============================================================
__device__ __forceinline__ float gelu_exact(float v)
{
    return 0.5f * v * (1.0f + erff(v * 0.70710678118654752f));
}

#define F_A  0u
#define F_BH 16384u
#define F_BL 32768u

__global__ __launch_bounds__(256) void ff_mma_kernel(
    const float* __restrict__ bf, float* __restrict__ out)
{
    extern __shared__ char dsm[];
    const uint32_t sb = smem_u32(dsm);

    const int tid = threadIdx.x;
    const int wid = tid >> 5;
    const int lane = tid & 31;
    const int warp_m = wid >> 2;
    const int warp_n = wid & 3;
    const int c0 = blockIdx.x * 128;
    const int t0 = blockIdx.y * 128;

    {
        const char* pA  = (const char*)g_sumh;
        const char* pBh = (const char*)g_wfhi;
        const char* pBl = (const char*)g_wflo;
        #pragma unroll
        for (int i = 0; i < 4; i++) {
            int chunk = tid + i * 256;
            int r = chunk >> 3;
            int c = chunk & 7;
            uint32_t off = r * 128 + (((uint32_t)(c ^ (r & 7))) << 4);
            size_t ga = ((size_t)(t0 + r) * DHH) * 2 + c * 16;
            size_t gb = ((size_t)(c0 + r) * DHH) * 2 + c * 16;
            CP16(sb + F_A + off, pA + ga);
            CP16(sb + F_BH + off, pBh + gb);
            CP16(sb + F_BL + off, pBl + gb);
        }
        CP_COMMIT();
        CP_WAIT0();
        __syncthreads();
    }

    float acc[4][4][4];
    #pragma unroll
    for (int i = 0; i < 4; i++)
        #pragma unroll
        for (int j = 0; j < 4; j++)
            #pragma unroll
            for (int v = 0; v < 4; v++) acc[i][j][v] = 0.f;

    #pragma unroll
    for (int ks = 0; ks < 4; ks++) {
        uint32_t ah[16];
        #pragma unroll
        for (int mt = 0; mt < 4; mt++) {
            int r = warp_m * 64 + mt * 16 + (lane & 15);
            int c = 2 * ks + (lane >> 4);
            uint32_t off = r * 128 + (((uint32_t)(c ^ (r & 7))) << 4);
            LDSM_X4(&ah[mt * 4], sb + F_A + off);
        }
        uint32_t bh[8], bl[8];
        #pragma unroll
        for (int bt = 0; bt < 2; bt++) {
            int nr = warp_n * 32 + bt * 16 + ((lane >> 4) << 3) + (lane & 7);
            int c = 2 * ks + ((lane >> 3) & 1);
            uint32_t off = nr * 128 + (((uint32_t)(c ^ (nr & 7))) << 4);
            LDSM_X4(&bh[bt * 4], sb + F_BH + off);
            LDSM_X4(&bl[bt * 4], sb + F_BL + off);
        }
        #pragma unroll
        for (int mt = 0; mt < 4; mt++)
            #pragma unroll
            for (int nt = 0; nt < 4; nt++) {
                int bi = (nt >> 1) * 4 + (nt & 1) * 2;
                MMAF16(acc[mt][nt], &ah[mt * 4], &bh[bi]);
            }
        #pragma unroll
        for (int mt = 0; mt < 4; mt++)
            #pragma unroll
            for (int nt = 0; nt < 4; nt++) {
                int bi = (nt >> 1) * 4 + (nt & 1) * 2;
                MMAF16(acc[mt][nt], &ah[mt * 4], &bl[bi]);
            }
    }

    #pragma unroll
    for (int nt = 0; nt < 4; nt++) {
        int col = c0 + warp_n * 32 + nt * 8 + (lane & 3) * 2;
        float b0v = bf[col];
        float b1v = bf[col + 1];
        #pragma unroll
        for (int mt = 0; mt < 4; mt++) {
            #pragma unroll
            for (int half = 0; half < 2; half++) {
                int tok = t0 + warp_m * 64 + mt * 16 + (lane >> 2) + half * 8;
                float2 r2;
                r2.x = gelu_exact(acc[mt][nt][half * 2]     + b0v);
                r2.y = gelu_exact(acc[mt][nt][half * 2 + 1] + b1v);
                *(float2*)&out[(size_t)tok * DD + col] = r2;
            }
        }
    }
}

// ============================================================
extern "C" void kernel_launch(void* const* d_in, const int* in_sizes, int n_in,
                              void* d_out, int out_size)
{
    const float* x  = (const float*)d_in[0];
    const float* Wq = (const float*)d_in[1];
    const float* bq = (const float*)d_in[2];
    const float* Wk = (const float*)d_in[3];
    const float* bk = (const float*)d_in[4];
    const float* Wv = (const float*)d_in[5];
    const float* bv = (const float*)d_in[6];
    const float* Wf = (const float*)d_in[7];
    const float* bf = (const float*)d_in[8];
    float* out = (float*)d_out;

    static const int QKV_SMEM = 98304;    // 2 stages x 48KB (x2 CTAs = 192KB/SM)
    static const int ATT_SMEM = 73728;    // 2 stages x 32KB + Q 8KB
    static const int FF_SMEM  = 49152;
    cudaFuncSetAttribute(qkv_mma_kernel,
                         cudaFuncAttributeMaxDynamicSharedMemorySize, QKV_SMEM);
    cudaFuncSetAttribute(attn_mma_kernel,
                         cudaFuncAttributeMaxDynamicSharedMemorySize, ATT_SMEM);
    cudaFuncSetAttribute(ff_mma_kernel,
                         cudaFuncAttributeMaxDynamicSharedMemorySize, FF_SMEM);

    split_all_kernel<<<4096 + 768 + 16, 256>>>(x, Wq, Wk, Wv, Wf);

    dim3 gMMA(NFLAT / 128, (BB * SS) / 128);
    qkv_mma_kernel<<<gMMA, 256, QKV_SMEM>>>(bq, bk, bv);

    dim3 gAtt(16, 64);
    attn_mma_kernel<<<gAtt, 128, ATT_SMEM>>>();

    headsum_kernel<<<(BB * SS * DHH / 2) / 256, 256>>>();

    dim3 gFF(DD / 128, (BB * SS) / 128);
    ff_mma_kernel<<<gFF, 256, FF_SMEM>>>(bf, out);
}